// round 5
// baseline (speedup 1.0000x reference)
#include <cuda_runtime.h>
#include <math.h>
#include <stdint.h>

#define N_NODES 50000
#define D2      512
#define HEADS   4
#define CH      128
#define NEG     0.2f
#define MAXE    450048   // 400000 edges + 50000 self loops, padded

// ---------------- scratch (static device globals; no runtime alloc) -------
__device__ __align__(128) float g_bufA[(size_t)N_NODES * D2];
__device__ __align__(128) float g_bufB[(size_t)N_NODES * D2];
__device__ __align__(128) float g_xl  [(size_t)N_NODES * D2];
__device__ __align__(128) float g_xr  [(size_t)N_NODES * D2];
__device__ __align__(128) float g_p   [(size_t)MAXE * HEADS];
__device__ __align__(128) float g_den [(size_t)N_NODES * HEADS];

// ---------------- fp32 tiled SGEMM: C[M,N] = A[M,K] @ B[K,N] (+bias) ------
// 128x128 tile, BK=16, 256 threads, 8x8 per thread.
__global__ void __launch_bounds__(256)
sgemm_kernel(const float* __restrict__ A, const float* __restrict__ B,
             float* __restrict__ C, int M, int N, int K,
             const float* __restrict__ bias)
{
    __shared__ float As[16][128];
    __shared__ float Bs[16][128];

    const int tid  = threadIdx.x;
    const int tx   = tid & 15;
    const int ty   = tid >> 4;
    const int row0 = blockIdx.y * 128;
    const int col0 = blockIdx.x * 128;

    float acc[8][8];
#pragma unroll
    for (int i = 0; i < 8; i++)
#pragma unroll
        for (int j = 0; j < 8; j++) acc[i][j] = 0.f;

    const int a_r = tid >> 1;          // 0..127
    const int a_c = (tid & 1) * 8;     // 0 or 8
    const int b_r = tid >> 5;          // 0..7
    const int b_c = (tid & 31) * 4;    // 0..124

    for (int k0 = 0; k0 < K; k0 += 16) {
        // A tile (transposed into As[k][m])
#pragma unroll
        for (int i = 0; i < 8; i++) {
            int kk = k0 + a_c + i;
            float v = 0.f;
            if (row0 + a_r < M && kk < K)
                v = A[(size_t)(row0 + a_r) * K + kk];
            As[a_c + i][a_r] = v;
        }
        // B tile
#pragma unroll
        for (int i = 0; i < 2; i++) {
            int kk = k0 + b_r + i * 8;
#pragma unroll
            for (int j = 0; j < 4; j++) {
                int cc = col0 + b_c + j;
                float v = 0.f;
                if (kk < K && cc < N)
                    v = B[(size_t)kk * N + cc];
                Bs[b_r + i * 8][b_c + j] = v;
            }
        }
        __syncthreads();

#pragma unroll
        for (int kk = 0; kk < 16; kk++) {
            float a[8], b[8];
#pragma unroll
            for (int i = 0; i < 4; i++) {
                a[i]     = As[kk][ty * 4 + i];
                a[4 + i] = As[kk][64 + ty * 4 + i];
            }
#pragma unroll
            for (int j = 0; j < 4; j++) {
                b[j]     = Bs[kk][tx * 4 + j];
                b[4 + j] = Bs[kk][64 + tx * 4 + j];
            }
#pragma unroll
            for (int i = 0; i < 8; i++)
#pragma unroll
                for (int j = 0; j < 8; j++)
                    acc[i][j] = fmaf(a[i], b[j], acc[i][j]);
        }
        __syncthreads();
    }

#pragma unroll
    for (int i = 0; i < 8; i++) {
        int r = row0 + ((i < 4) ? (ty * 4 + i) : (64 + ty * 4 + (i - 4)));
        if (r >= M) continue;
#pragma unroll
        for (int j = 0; j < 8; j++) {
            int c = col0 + ((j < 4) ? (tx * 4 + j) : (64 + tx * 4 + (j - 4)));
            if (c < N)
                C[(size_t)r * N + c] = acc[i][j] + (bias ? bias[c] : 0.f);
        }
    }
}

// ---------------- edge pass A: logits -> p = exp(logit), denom += p -------
// One warp per edge (edges >= E are implicit self loops).
// Softmax is shift-invariant: skipping the segment-max pass is exact as long
// as exp() doesn't overflow; logits here are O(1).
__global__ void edge_logits_kernel(const float* __restrict__ xl,
                                   const float* __restrict__ xr,
                                   const int* __restrict__ ei,
                                   int E, int ET,
                                   const float* __restrict__ att,
                                   float* __restrict__ p,
                                   float* __restrict__ denom)
{
    int warp = (blockIdx.x * blockDim.x + threadIdx.x) >> 5;
    int lane = threadIdx.x & 31;
    if (warp >= ET) return;

    int src, dst;
    if (warp < E) { src = ei[warp]; dst = ei[(size_t)E + warp]; }
    else          { src = dst = warp - E; }

    const float4* xl4 = (const float4*)(xl + (size_t)src * D2);
    const float4* xr4 = (const float4*)(xr + (size_t)dst * D2);
    const float4* at4 = (const float4*)att;

    float acc[HEADS];
#pragma unroll
    for (int h = 0; h < HEADS; h++) {
        float4 a = xl4[h * 32 + lane];
        float4 b = xr4[h * 32 + lane];
        float4 w = at4[h * 32 + lane];
        float vx = a.x + b.x; vx = vx > 0.f ? vx : NEG * vx;
        float vy = a.y + b.y; vy = vy > 0.f ? vy : NEG * vy;
        float vz = a.z + b.z; vz = vz > 0.f ? vz : NEG * vz;
        float vw = a.w + b.w; vw = vw > 0.f ? vw : NEG * vw;
        acc[h] = vx * w.x + vy * w.y + vz * w.z + vw * w.w;
    }
#pragma unroll
    for (int off = 16; off > 0; off >>= 1)
#pragma unroll
        for (int h = 0; h < HEADS; h++)
            acc[h] += __shfl_xor_sync(0xffffffffu, acc[h], off);

    if (lane == 0) {
#pragma unroll
        for (int h = 0; h < HEADS; h++) {
            float pv = __expf(acc[h]);
            p[(size_t)warp * HEADS + h] = pv;
            atomicAdd(denom + (size_t)dst * HEADS + h, pv);
        }
    }
}

// ---------------- edge pass B: out[dst] += alpha * xl[src] ----------------
__global__ void edge_aggregate_kernel(const float* __restrict__ xl,
                                      const float* __restrict__ p,
                                      const float* __restrict__ denom,
                                      const int* __restrict__ ei,
                                      int E, int ET,
                                      float* __restrict__ out)
{
    int warp = (blockIdx.x * blockDim.x + threadIdx.x) >> 5;
    int lane = threadIdx.x & 31;
    if (warp >= ET) return;

    int src, dst;
    if (warp < E) { src = ei[warp]; dst = ei[(size_t)E + warp]; }
    else          { src = dst = warp - E; }

    float av = 0.f;
    if (lane < HEADS)
        av = p[(size_t)warp * HEADS + lane] / denom[(size_t)dst * HEADS + lane];
    float al[HEADS];
#pragma unroll
    for (int h = 0; h < HEADS; h++)
        al[h] = __shfl_sync(0xffffffffu, av, h);

    const float4* xl4 = (const float4*)(xl + (size_t)src * D2);
    float4*       o4  = (float4*)(out + (size_t)dst * D2);
#pragma unroll
    for (int h = 0; h < HEADS; h++) {
        float4 v = xl4[h * 32 + lane];
        float  a = al[h];
        float4* addr = o4 + h * 32 + lane;
        asm volatile("red.global.add.v4.f32 [%0], {%1, %2, %3, %4};"
                     :: "l"(addr), "f"(v.x * a), "f"(v.y * a),
                        "f"(v.z * a), "f"(v.w * a)
                     : "memory");
    }
}

// ---------------- elementwise: buf = elu(buf + bias) ----------------------
__global__ void elu_bias_kernel(float* __restrict__ buf,
                                const float* __restrict__ bias, int n)
{
    int i = blockIdx.x * blockDim.x + threadIdx.x;
    if (i < n) {
        float v = buf[i] + bias[i & (D2 - 1)];
        buf[i] = v > 0.f ? v : expm1f(v);
    }
}

// ---------------- host orchestration --------------------------------------
static void run_layer(const float* act, int K,
                      const float* Wl, const float* Wr,
                      const float* att, const float* bias,
                      const int* ei, int E, int ET,
                      float* xl, float* xr, float* p, float* den,
                      float* outbuf)
{
    dim3 gg((D2 + 127) / 128, (N_NODES + 127) / 128);
    sgemm_kernel<<<gg, 256>>>(act, Wl, xl, N_NODES, D2, K, nullptr);
    sgemm_kernel<<<gg, 256>>>(act, Wr, xr, N_NODES, D2, K, nullptr);

    cudaMemsetAsync(den, 0, (size_t)N_NODES * HEADS * sizeof(float));
    int eb = (ET * 32 + 255) / 256;
    edge_logits_kernel<<<eb, 256>>>(xl, xr, ei, E, ET, att, p, den);

    cudaMemsetAsync(outbuf, 0, (size_t)N_NODES * D2 * sizeof(float));
    edge_aggregate_kernel<<<eb, 256>>>(xl, p, den, ei, E, ET, outbuf);

    int n = N_NODES * D2;
    elu_bias_kernel<<<(n + 255) / 256, 256>>>(outbuf, bias, n);
}

extern "C" void kernel_launch(void* const* d_in, const int* in_sizes, int n_in,
                              void* d_out, int out_size)
{
    const float* x    = (const float*)d_in[0];
    const int*   ei   = (const int*)d_in[1];   // JAX default x64-disabled => int32
    const float* W1l  = (const float*)d_in[2];
    const float* W1r  = (const float*)d_in[3];
    const float* att1 = (const float*)d_in[4];
    const float* b1   = (const float*)d_in[5];
    const float* W2l  = (const float*)d_in[6];
    const float* W2r  = (const float*)d_in[7];
    const float* att2 = (const float*)d_in[8];
    const float* b2   = (const float*)d_in[9];
    const float* Wc   = (const float*)d_in[10];
    const float* bc   = (const float*)d_in[11];

    const int E    = in_sizes[1] / 2;          // 400000
    const int ET   = E + N_NODES;              // + self loops
    const int K_in = in_sizes[0] / N_NODES;    // 55

    float *bufA, *bufB, *xl, *xr, *p, *den;
    cudaGetSymbolAddress((void**)&bufA, g_bufA);
    cudaGetSymbolAddress((void**)&bufB, g_bufB);
    cudaGetSymbolAddress((void**)&xl,   g_xl);
    cudaGetSymbolAddress((void**)&xr,   g_xr);
    cudaGetSymbolAddress((void**)&p,    g_p);
    cudaGetSymbolAddress((void**)&den,  g_den);

    // layer 1: x -> bufB
    run_layer(x, K_in, W1l, W1r, att1, b1, ei, E, ET, xl, xr, p, den, bufB);
    // layer 2: bufB -> bufA
    run_layer(bufB, D2, W2l, W2r, att2, b2, ei, E, ET, xl, xr, p, den, bufA);
    // layer 3 (conv2 applied again): bufA -> bufB
    run_layer(bufA, D2, W2l, W2r, att2, b2, ei, E, ET, xl, xr, p, den, bufB);

    // classifier: d_out = bufB @ Wc + bc   (N = 49)
    dim3 gc((49 + 127) / 128, (N_NODES + 127) / 128);
    sgemm_kernel<<<gc, 256>>>(bufB, Wc, (float*)d_out, N_NODES, 49, D2, bc);
}

// round 9
// speedup vs baseline: 1.7996x; 1.7996x over previous
#include <cuda_runtime.h>
#include <cuda_bf16.h>
#include <math.h>
#include <stdint.h>

#define N_NODES 50000
#define M_PAD   50048          // 391 * 128
#define D2      512
#define HEADS   4
#define CH      128
#define NEG     0.2f
#define MAXE    450048
#define K3      1536           // 3 * 512 (hi|hi|lo split along K)
#define BK      64             // bf16 K-elems per smem stage (128B rows, SW128)
#define NSTG    (K3 / BK)      // 24 stages

// ---------------- scratch (static device globals; no runtime alloc) -------
__device__ __align__(128) float g_bufA[(size_t)M_PAD * D2];
__device__ __align__(128) float g_bufB[(size_t)M_PAD * D2];
__device__ __align__(128) float g_xl  [(size_t)M_PAD * D2];
__device__ __align__(128) float g_xr  [(size_t)M_PAD * D2];
__device__ __align__(128) float g_p   [(size_t)MAXE * HEADS];
__device__ __align__(128) float g_den [(size_t)N_NODES * HEADS];
__device__ __align__(128) __nv_bfloat16 g_a2 [(size_t)M_PAD * K3];   // A' = [hi|hi|lo]
__device__ __align__(128) __nv_bfloat16 g_btl[(size_t)D2 * K3];      // B' (W2l), [N,K'] K-major
__device__ __align__(128) __nv_bfloat16 g_btr[(size_t)D2 * K3];      // B' (W2r)

// ======================= helpers ===========================================
__device__ __forceinline__ uint32_t smem_u32(const void* p) {
    uint32_t a;
    asm("{ .reg .u64 t; cvta.to.shared.u64 t, %1; cvt.u32.u64 %0, t; }"
        : "=r"(a) : "l"(p));
    return a;
}
__device__ __forceinline__ uint32_t lds32(uint32_t addr) {
    uint32_t v;
    asm volatile("ld.shared.b32 %0, [%1];" : "=r"(v) : "r"(addr));
    return v;
}
// SW128 swizzled byte address within a 128-row x 128-byte tile.
// kb: byte offset within the 128-byte row.
__device__ __forceinline__ uint32_t tile_addr(int r, int kb) {
    return (uint32_t)(r * 128 + ((((kb >> 4) ^ (r & 7))) << 4) + (kb & 15));
}
#define SW128(o) ((o) ^ (((o) >> 3) & 0x70))

__device__ __forceinline__ void mma16816(float* c, const uint32_t* a, const uint32_t* b) {
    asm volatile(
        "mma.sync.aligned.m16n8k16.row.col.f32.bf16.bf16.f32 "
        "{%0,%1,%2,%3}, {%4,%5,%6,%7}, {%8,%9}, {%0,%1,%2,%3};"
        : "+f"(c[0]), "+f"(c[1]), "+f"(c[2]), "+f"(c[3])
        : "r"(a[0]), "r"(a[1]), "r"(a[2]), "r"(a[3]), "r"(b[0]), "r"(b[1]));
}

// ================= mma.sync GEMM: C[M_PAD,512] = A'[M_PAD,K3] @ B'[512,K3]^T
// 128x128 CTA tile, 8 warps (2x4), warp tile 64x32, BK=64 double-buffered
// cp.async (SW128), bf16 hi/lo split accumulated in fp32.
__device__ __forceinline__ void load_tile(uint32_t sdst, const __nv_bfloat16* __restrict__ g,
                                          size_t row0, int k0) {
    const char* gb = (const char*)g + (row0 * (size_t)K3 + (size_t)k0) * 2;
#pragma unroll
    for (int i = 0; i < 4; i++) {
        int c = threadIdx.x + i * 256;       // 1024 16B chunks
        int r = c >> 3;
        int o = (c & 7) * 16;
        uint32_t dst = sdst + SW128((uint32_t)(r * 128 + o));
        asm volatile("cp.async.cg.shared.global [%0], [%1], 16;"
                     :: "r"(dst), "l"(gb + (size_t)r * (K3 * 2) + o) : "memory");
    }
}

__global__ void __launch_bounds__(256, 2)
mma_gemm_kernel(const __nv_bfloat16* __restrict__ A2,
                const __nv_bfloat16* __restrict__ Bt,
                float* __restrict__ C)
{
    extern __shared__ char dsm[];            // 2 stages x (16KB A + 16KB B) = 64KB
    const int tid    = threadIdx.x;
    const int wid    = tid >> 5;
    const int lane   = tid & 31;
    const int warp_m = wid >> 2;             // 0..1
    const int warp_n = wid & 3;              // 0..3
    const int gID    = lane >> 2;            // 0..7
    const int l4     = lane & 3;             // 0..3
    const size_t m0  = (size_t)blockIdx.y * 128;
    const int    n0  = blockIdx.x * 128;
    const uint32_t smb = smem_u32(dsm);

    float acc[4][4][4];
#pragma unroll
    for (int i = 0; i < 4; i++)
#pragma unroll
        for (int j = 0; j < 4; j++)
#pragma unroll
            for (int q = 0; q < 4; q++) acc[i][j][q] = 0.f;

    // preload stages 0, 1
    load_tile(smb,                 A2, m0, 0);
    load_tile(smb + 16384,         Bt, (size_t)n0, 0);
    asm volatile("cp.async.commit_group;" ::: "memory");
    load_tile(smb + 32768,         A2, m0, BK);
    load_tile(smb + 32768 + 16384, Bt, (size_t)n0, BK);
    asm volatile("cp.async.commit_group;" ::: "memory");

    for (int s = 0; s < NSTG; s++) {
        if (s < NSTG - 1) asm volatile("cp.async.wait_group 1;" ::: "memory");
        else              asm volatile("cp.async.wait_group 0;" ::: "memory");
        __syncthreads();

        const int b = s & 1;
        const uint32_t As = smb + b * 32768;
        const uint32_t Bs = As + 16384;

#pragma unroll
        for (int ks = 0; ks < 4; ks++) {     // 4 x K=16 per stage
            const int kb = ks * 32 + l4 * 4; // byte col of this lane's low pair
            uint32_t a[4][4], bb[4][2];
#pragma unroll
            for (int mf = 0; mf < 4; mf++) {
                int r0 = warp_m * 64 + mf * 16 + gID;
                a[mf][0] = lds32(As + tile_addr(r0,     kb));
                a[mf][1] = lds32(As + tile_addr(r0 + 8, kb));
                a[mf][2] = lds32(As + tile_addr(r0,     kb + 16));
                a[mf][3] = lds32(As + tile_addr(r0 + 8, kb + 16));
            }
#pragma unroll
            for (int nf = 0; nf < 4; nf++) {
                int nr = warp_n * 32 + nf * 8 + gID;
                bb[nf][0] = lds32(Bs + tile_addr(nr, kb));
                bb[nf][1] = lds32(Bs + tile_addr(nr, kb + 16));
            }
#pragma unroll
            for (int mf = 0; mf < 4; mf++)
#pragma unroll
                for (int nf = 0; nf < 4; nf++)
                    mma16816(acc[mf][nf], a[mf], bb[nf]);
        }
        __syncthreads();

        const int t = s + 2;
        if (t < NSTG) {
            load_tile(smb + b * 32768,         A2, m0, t * BK);
            load_tile(smb + b * 32768 + 16384, Bt, (size_t)n0, t * BK);
            asm volatile("cp.async.commit_group;" ::: "memory");
        }
    }

    // epilogue: write fp32 accumulators (rows all < M_PAD, no bounds checks)
    float* Cbase = C + m0 * D2 + n0;
#pragma unroll
    for (int mf = 0; mf < 4; mf++) {
        int r0 = warp_m * 64 + mf * 16 + gID;
#pragma unroll
        for (int nf = 0; nf < 4; nf++) {
            int cc = warp_n * 32 + nf * 8 + l4 * 2;
            *(float2*)(Cbase + (size_t)r0 * D2 + cc) =
                make_float2(acc[mf][nf][0], acc[mf][nf][1]);
            *(float2*)(Cbase + (size_t)(r0 + 8) * D2 + cc) =
                make_float2(acc[mf][nf][2], acc[mf][nf][3]);
        }
    }
}

// ---------------- fp32 split conversions -----------------------------------
__global__ void cvt_act_kernel(const float* __restrict__ act,
                               __nv_bfloat16* __restrict__ A2, int total)
{
    int i = blockIdx.x * blockDim.x + threadIdx.x;
    if (i >= total) return;
    int m = i >> 9, k = i & 511;
    float v = act[i];
    __nv_bfloat16 h = __float2bfloat16(v);
    __nv_bfloat16 l = __float2bfloat16(v - __bfloat162float(h));
    __nv_bfloat16* row = A2 + (size_t)m * K3;
    row[k] = h; row[512 + k] = h; row[1024 + k] = l;
}
__global__ void cvt_wt_kernel(const float* __restrict__ W,   // [K=512][N=512]
                              __nv_bfloat16* __restrict__ Bt) // [N=512][K3]
{
    int i = blockIdx.x * blockDim.x + threadIdx.x;
    if (i >= D2 * D2) return;
    int k = i >> 9, n = i & 511;
    float v = W[i];
    __nv_bfloat16 h = __float2bfloat16(v);
    __nv_bfloat16 l = __float2bfloat16(v - __bfloat162float(h));
    __nv_bfloat16* row = Bt + (size_t)n * K3;
    row[k] = h; row[512 + k] = l; row[1024 + k] = h;
}

// ---------------- fp32 tiled SGEMM (layer 1 + classifier) ------------------
__global__ void __launch_bounds__(256)
sgemm_kernel(const float* __restrict__ A, const float* __restrict__ B,
             float* __restrict__ C, int M, int N, int K,
             const float* __restrict__ bias)
{
    __shared__ float As[16][128];
    __shared__ float Bs[16][128];
    const int tid = threadIdx.x;
    const int tx = tid & 15, ty = tid >> 4;
    const int row0 = blockIdx.y * 128, col0 = blockIdx.x * 128;
    float acc[8][8];
#pragma unroll
    for (int i = 0; i < 8; i++)
#pragma unroll
        for (int j = 0; j < 8; j++) acc[i][j] = 0.f;
    const int a_r = tid >> 1, a_c = (tid & 1) * 8;
    const int b_r = tid >> 5, b_c = (tid & 31) * 4;
    for (int k0 = 0; k0 < K; k0 += 16) {
#pragma unroll
        for (int i = 0; i < 8; i++) {
            int kk = k0 + a_c + i;
            float v = 0.f;
            if (row0 + a_r < M && kk < K) v = A[(size_t)(row0 + a_r) * K + kk];
            As[a_c + i][a_r] = v;
        }
#pragma unroll
        for (int i = 0; i < 2; i++) {
            int kk = k0 + b_r + i * 8;
#pragma unroll
            for (int j = 0; j < 4; j++) {
                int cc = col0 + b_c + j;
                float v = 0.f;
                if (kk < K && cc < N) v = B[(size_t)kk * N + cc];
                Bs[b_r + i * 8][b_c + j] = v;
            }
        }
        __syncthreads();
#pragma unroll
        for (int kk = 0; kk < 16; kk++) {
            float a[8], b[8];
#pragma unroll
            for (int i = 0; i < 4; i++) {
                a[i] = As[kk][ty * 4 + i];
                a[4 + i] = As[kk][64 + ty * 4 + i];
            }
#pragma unroll
            for (int j = 0; j < 4; j++) {
                b[j] = Bs[kk][tx * 4 + j];
                b[4 + j] = Bs[kk][64 + tx * 4 + j];
            }
#pragma unroll
            for (int i = 0; i < 8; i++)
#pragma unroll
                for (int j = 0; j < 8; j++)
                    acc[i][j] = fmaf(a[i], b[j], acc[i][j]);
        }
        __syncthreads();
    }
#pragma unroll
    for (int i = 0; i < 8; i++) {
        int r = row0 + ((i < 4) ? (ty * 4 + i) : (64 + ty * 4 + (i - 4)));
        if (r >= M) continue;
#pragma unroll
        for (int j = 0; j < 8; j++) {
            int c = col0 + ((j < 4) ? (tx * 4 + j) : (64 + tx * 4 + (j - 4)));
            if (c < N) C[(size_t)r * N + c] = acc[i][j] + (bias ? bias[c] : 0.f);
        }
    }
}

// ---------------- edge pass A: p = exp(logit), denom += p ------------------
__global__ void edge_logits_kernel(const float* __restrict__ xl,
                                   const float* __restrict__ xr,
                                   const int* __restrict__ ei,
                                   int E, int ET,
                                   const float* __restrict__ att,
                                   float* __restrict__ p,
                                   float* __restrict__ denom)
{
    int warp = (blockIdx.x * blockDim.x + threadIdx.x) >> 5;
    int lane = threadIdx.x & 31;
    if (warp >= ET) return;
    int src, dst;
    if (warp < E) { src = ei[warp]; dst = ei[(size_t)E + warp]; }
    else          { src = dst = warp - E; }

    const float4* xl4 = (const float4*)(xl + (size_t)src * D2);
    const float4* xr4 = (const float4*)(xr + (size_t)dst * D2);
    const float4* at4 = (const float4*)att;
    float acc[HEADS];
#pragma unroll
    for (int h = 0; h < HEADS; h++) {
        float4 a = xl4[h * 32 + lane];
        float4 b = xr4[h * 32 + lane];
        float4 w = at4[h * 32 + lane];
        float vx = a.x + b.x; vx = vx > 0.f ? vx : NEG * vx;
        float vy = a.y + b.y; vy = vy > 0.f ? vy : NEG * vy;
        float vz = a.z + b.z; vz = vz > 0.f ? vz : NEG * vz;
        float vw = a.w + b.w; vw = vw > 0.f ? vw : NEG * vw;
        acc[h] = vx * w.x + vy * w.y + vz * w.z + vw * w.w;
    }
#pragma unroll
    for (int off = 16; off > 0; off >>= 1)
#pragma unroll
        for (int h = 0; h < HEADS; h++)
            acc[h] += __shfl_xor_sync(0xffffffffu, acc[h], off);
    if (lane == 0) {
#pragma unroll
        for (int h = 0; h < HEADS; h++) {
            float pv = __expf(acc[h]);
            p[(size_t)warp * HEADS + h] = pv;
            atomicAdd(denom + (size_t)dst * HEADS + h, pv);
        }
    }
}

// ---------------- edge pass B: out[dst] += alpha * xl[src] -----------------
__global__ void edge_aggregate_kernel(const float* __restrict__ xl,
                                      const float* __restrict__ p,
                                      const float* __restrict__ denom,
                                      const int* __restrict__ ei,
                                      int E, int ET,
                                      float* __restrict__ out)
{
    int warp = (blockIdx.x * blockDim.x + threadIdx.x) >> 5;
    int lane = threadIdx.x & 31;
    if (warp >= ET) return;
    int src, dst;
    if (warp < E) { src = ei[warp]; dst = ei[(size_t)E + warp]; }
    else          { src = dst = warp - E; }

    float av = 0.f;
    if (lane < HEADS)
        av = p[(size_t)warp * HEADS + lane] / denom[(size_t)dst * HEADS + lane];
    float al[HEADS];
#pragma unroll
    for (int h = 0; h < HEADS; h++)
        al[h] = __shfl_sync(0xffffffffu, av, h);

    const float4* xl4 = (const float4*)(xl + (size_t)src * D2);
    float4*       o4  = (float4*)(out + (size_t)dst * D2);
#pragma unroll
    for (int h = 0; h < HEADS; h++) {
        float4 v = xl4[h * 32 + lane];
        float  a = al[h];
        float4* addr = o4 + h * 32 + lane;
        asm volatile("red.global.add.v4.f32 [%0], {%1, %2, %3, %4};"
                     :: "l"(addr), "f"(v.x * a), "f"(v.y * a),
                        "f"(v.z * a), "f"(v.w * a)
                     : "memory");
    }
}

// ---------------- elementwise: buf = elu(buf + bias) -----------------------
__global__ void elu_bias_kernel(float* __restrict__ buf,
                                const float* __restrict__ bias, int n)
{
    int i = blockIdx.x * blockDim.x + threadIdx.x;
    if (i < n) {
        float v = buf[i] + bias[i & (D2 - 1)];
        buf[i] = v > 0.f ? v : expm1f(v);
    }
}

// ---------------- host orchestration ---------------------------------------
static void run_edges(const float* xl, const float* xr,
                      const float* att, const float* bias,
                      const int* ei, int E, int ET,
                      float* p, float* den, float* outbuf)
{
    cudaMemsetAsync(den, 0, (size_t)N_NODES * HEADS * sizeof(float));
    int eb = (ET * 32 + 255) / 256;
    edge_logits_kernel<<<eb, 256>>>(xl, xr, ei, E, ET, att, p, den);
    cudaMemsetAsync(outbuf, 0, (size_t)M_PAD * D2 * sizeof(float));   // pad rows stay 0
    edge_aggregate_kernel<<<eb, 256>>>(xl, p, den, ei, E, ET, outbuf);
    int n = N_NODES * D2;
    elu_bias_kernel<<<(n + 255) / 256, 256>>>(outbuf, bias, n);
}

extern "C" void kernel_launch(void* const* d_in, const int* in_sizes, int n_in,
                              void* d_out, int out_size)
{
    const float* x    = (const float*)d_in[0];
    const int*   ei   = (const int*)d_in[1];
    const float* W1l  = (const float*)d_in[2];
    const float* W1r  = (const float*)d_in[3];
    const float* att1 = (const float*)d_in[4];
    const float* b1   = (const float*)d_in[5];
    const float* W2l  = (const float*)d_in[6];
    const float* W2r  = (const float*)d_in[7];
    const float* att2 = (const float*)d_in[8];
    const float* b2   = (const float*)d_in[9];
    const float* Wc   = (const float*)d_in[10];
    const float* bc   = (const float*)d_in[11];

    const int E    = in_sizes[1] / 2;
    const int ET   = E + N_NODES;
    const int K_in = in_sizes[0] / N_NODES;   // 55

    float *bufA, *bufB, *xl, *xr, *p, *den;
    __nv_bfloat16 *a2, *btl, *btr;
    cudaGetSymbolAddress((void**)&bufA, g_bufA);
    cudaGetSymbolAddress((void**)&bufB, g_bufB);
    cudaGetSymbolAddress((void**)&xl,   g_xl);
    cudaGetSymbolAddress((void**)&xr,   g_xr);
    cudaGetSymbolAddress((void**)&p,    g_p);
    cudaGetSymbolAddress((void**)&den,  g_den);
    cudaGetSymbolAddress((void**)&a2,   g_a2);
    cudaGetSymbolAddress((void**)&btl,  g_btl);
    cudaGetSymbolAddress((void**)&btr,  g_btr);

    cudaFuncSetAttribute(mma_gemm_kernel,
                         cudaFuncAttributeMaxDynamicSharedMemorySize, 65536);

    // W2 split conversion (used by layers 2 and 3)
    cvt_wt_kernel<<<(D2 * D2 + 255) / 256, 256>>>(W2l, btl);
    cvt_wt_kernel<<<(D2 * D2 + 255) / 256, 256>>>(W2r, btr);

    // ---- layer 1 (K=55, SIMT GEMMs) -> bufB ----
    {
        dim3 gg(D2 / 128, (N_NODES + 127) / 128);
        sgemm_kernel<<<gg, 256>>>(x, W1l, xl, N_NODES, D2, K_in, nullptr);
        sgemm_kernel<<<gg, 256>>>(x, W1r, xr, N_NODES, D2, K_in, nullptr);
        run_edges(xl, xr, att1, b1, ei, E, ET, p, den, bufB);
    }

    // ---- layers 2 & 3 (tensor-core GEMMs via mma.sync) ----
    const int cvt_total = M_PAD * D2;
    dim3 tg(D2 / 128, M_PAD / 128);   // (4, 391)

    // layer 2: bufB -> bufA
    cvt_act_kernel<<<(cvt_total + 255) / 256, 256>>>(bufB, a2, cvt_total);
    mma_gemm_kernel<<<tg, 256, 65536>>>(a2, btl, xl);
    mma_gemm_kernel<<<tg, 256, 65536>>>(a2, btr, xr);
    run_edges(xl, xr, att2, b2, ei, E, ET, p, den, bufA);

    // layer 3 (conv2 again): bufA -> bufB
    cvt_act_kernel<<<(cvt_total + 255) / 256, 256>>>(bufA, a2, cvt_total);
    mma_gemm_kernel<<<tg, 256, 65536>>>(a2, btl, xl);
    mma_gemm_kernel<<<tg, 256, 65536>>>(a2, btr, xr);
    run_edges(xl, xr, att2, b2, ei, E, ET, p, den, bufB);

    // classifier: d_out = bufB @ Wc + bc   (N = 49)
    dim3 gc(1, (N_NODES + 127) / 128);
    sgemm_kernel<<<gc, 256>>>(bufB, Wc, (float*)d_out, N_NODES, 49, D2, bc);
}

// round 10
// speedup vs baseline: 2.4424x; 1.3572x over previous
#include <cuda_runtime.h>
#include <cuda_bf16.h>
#include <math.h>
#include <stdint.h>

#define N_NODES 50000
#define M_PAD   50048          // 391 * 128
#define D2      512
#define HEADS   4
#define NEG     0.2f
#define MAXE    450048
#define K3      1536           // 3 * 512 (hi|hi|lo split along K)
#define BK      64             // bf16 K-elems per smem stage (128B rows, SW128)
#define NSTG    (K3 / BK)      // 24 stages

// ---------------- scratch (static device globals; no runtime alloc) -------
__device__ __align__(128) float g_bufA[(size_t)M_PAD * D2];
__device__ __align__(128) float g_bufB[(size_t)M_PAD * D2];
__device__ __align__(128) float g_xl  [(size_t)M_PAD * D2];
__device__ __align__(128) float g_xr  [(size_t)M_PAD * D2];
__device__ __align__(128) __nv_bfloat16 g_a2 [(size_t)M_PAD * K3];   // A' = [hi|hi|lo]
__device__ __align__(128) __nv_bfloat16 g_btl[(size_t)D2 * K3];      // B' (W2l)
__device__ __align__(128) __nv_bfloat16 g_btr[(size_t)D2 * K3];      // B' (W2r)
__device__ int g_deg[N_NODES];
__device__ int g_off[N_NODES + 1];
__device__ int g_cur[N_NODES];
__device__ int g_csr[MAXE];

// ======================= helpers ===========================================
__device__ __forceinline__ uint32_t smem_u32(const void* p) {
    uint32_t a;
    asm("{ .reg .u64 t; cvta.to.shared.u64 t, %1; cvt.u32.u64 %0, t; }"
        : "=r"(a) : "l"(p));
    return a;
}
__device__ __forceinline__ uint32_t lds32(uint32_t addr) {
    uint32_t v;
    asm volatile("ld.shared.b32 %0, [%1];" : "=r"(v) : "r"(addr));
    return v;
}
__device__ __forceinline__ uint32_t tile_addr(int r, int kb) {
    return (uint32_t)(r * 128 + ((((kb >> 4) ^ (r & 7))) << 4) + (kb & 15));
}
#define SW128(o) ((o) ^ (((o) >> 3) & 0x70))

__device__ __forceinline__ void mma16816(float* c, const uint32_t* a, const uint32_t* b) {
    asm volatile(
        "mma.sync.aligned.m16n8k16.row.col.f32.bf16.bf16.f32 "
        "{%0,%1,%2,%3}, {%4,%5,%6,%7}, {%8,%9}, {%0,%1,%2,%3};"
        : "+f"(c[0]), "+f"(c[1]), "+f"(c[2]), "+f"(c[3])
        : "r"(a[0]), "r"(a[1]), "r"(a[2]), "r"(a[3]), "r"(b[0]), "r"(b[1]));
}

// ================= mma.sync GEMM: C[M_PAD,512] = A'[M_PAD,K3] @ B'[512,K3]^T
__device__ __forceinline__ void load_tile(uint32_t sdst, const __nv_bfloat16* __restrict__ g,
                                          size_t row0, int k0) {
    const char* gb = (const char*)g + (row0 * (size_t)K3 + (size_t)k0) * 2;
#pragma unroll
    for (int i = 0; i < 4; i++) {
        int c = threadIdx.x + i * 256;       // 1024 16B chunks
        int r = c >> 3;
        int o = (c & 7) * 16;
        uint32_t dst = sdst + SW128((uint32_t)(r * 128 + o));
        asm volatile("cp.async.cg.shared.global [%0], [%1], 16;"
                     :: "r"(dst), "l"(gb + (size_t)r * (K3 * 2) + o) : "memory");
    }
}

__global__ void __launch_bounds__(256, 2)
mma_gemm_kernel(const __nv_bfloat16* __restrict__ A2,
                const __nv_bfloat16* __restrict__ Bt,
                float* __restrict__ C)
{
    extern __shared__ char dsm[];            // 2 stages x (16KB A + 16KB B) = 64KB
    const int tid    = threadIdx.x;
    const int wid    = tid >> 5;
    const int lane   = tid & 31;
    const int warp_m = wid >> 2;
    const int warp_n = wid & 3;
    const int gID    = lane >> 2;
    const int l4     = lane & 3;
    const size_t m0  = (size_t)blockIdx.y * 128;
    const int    n0  = blockIdx.x * 128;
    const uint32_t smb = smem_u32(dsm);

    float acc[4][4][4];
#pragma unroll
    for (int i = 0; i < 4; i++)
#pragma unroll
        for (int j = 0; j < 4; j++)
#pragma unroll
            for (int q = 0; q < 4; q++) acc[i][j][q] = 0.f;

    load_tile(smb,                 A2, m0, 0);
    load_tile(smb + 16384,         Bt, (size_t)n0, 0);
    asm volatile("cp.async.commit_group;" ::: "memory");
    load_tile(smb + 32768,         A2, m0, BK);
    load_tile(smb + 32768 + 16384, Bt, (size_t)n0, BK);
    asm volatile("cp.async.commit_group;" ::: "memory");

    for (int s = 0; s < NSTG; s++) {
        if (s < NSTG - 1) asm volatile("cp.async.wait_group 1;" ::: "memory");
        else              asm volatile("cp.async.wait_group 0;" ::: "memory");
        __syncthreads();

        const int b = s & 1;
        const uint32_t As = smb + b * 32768;
        const uint32_t Bs = As + 16384;

#pragma unroll
        for (int ks = 0; ks < 4; ks++) {
            const int kb = ks * 32 + l4 * 4;
            uint32_t a[4][4], bb[4][2];
#pragma unroll
            for (int mf = 0; mf < 4; mf++) {
                int r0 = warp_m * 64 + mf * 16 + gID;
                a[mf][0] = lds32(As + tile_addr(r0,     kb));
                a[mf][1] = lds32(As + tile_addr(r0 + 8, kb));
                a[mf][2] = lds32(As + tile_addr(r0,     kb + 16));
                a[mf][3] = lds32(As + tile_addr(r0 + 8, kb + 16));
            }
#pragma unroll
            for (int nf = 0; nf < 4; nf++) {
                int nr = warp_n * 32 + nf * 8 + gID;
                bb[nf][0] = lds32(Bs + tile_addr(nr, kb));
                bb[nf][1] = lds32(Bs + tile_addr(nr, kb + 16));
            }
#pragma unroll
            for (int mf = 0; mf < 4; mf++)
#pragma unroll
                for (int nf = 0; nf < 4; nf++)
                    mma16816(acc[mf][nf], a[mf], bb[nf]);
        }
        __syncthreads();

        const int t = s + 2;
        if (t < NSTG) {
            load_tile(smb + b * 32768,         A2, m0, t * BK);
            load_tile(smb + b * 32768 + 16384, Bt, (size_t)n0, t * BK);
            asm volatile("cp.async.commit_group;" ::: "memory");
        }
    }

    float* Cbase = C + m0 * D2 + n0;
#pragma unroll
    for (int mf = 0; mf < 4; mf++) {
        int r0 = warp_m * 64 + mf * 16 + gID;
#pragma unroll
        for (int nf = 0; nf < 4; nf++) {
            int cc = warp_n * 32 + nf * 8 + l4 * 2;
            *(float2*)(Cbase + (size_t)r0 * D2 + cc) =
                make_float2(acc[mf][nf][0], acc[mf][nf][1]);
            *(float2*)(Cbase + (size_t)(r0 + 8) * D2 + cc) =
                make_float2(acc[mf][nf][2], acc[mf][nf][3]);
        }
    }
}

// ---------------- fp32 split conversions -----------------------------------
__global__ void cvt_act_kernel(const float* __restrict__ act,
                               __nv_bfloat16* __restrict__ A2, int total)
{
    int i = blockIdx.x * blockDim.x + threadIdx.x;
    if (i >= total) return;
    int m = i >> 9, k = i & 511;
    float v = act[i];
    __nv_bfloat16 h = __float2bfloat16(v);
    __nv_bfloat16 l = __float2bfloat16(v - __bfloat162float(h));
    __nv_bfloat16* row = A2 + (size_t)m * K3;
    row[k] = h; row[512 + k] = h; row[1024 + k] = l;
}
__global__ void cvt_wt_kernel(const float* __restrict__ W,   // [K=512][N=512]
                              __nv_bfloat16* __restrict__ Bt) // [N=512][K3]
{
    int i = blockIdx.x * blockDim.x + threadIdx.x;
    if (i >= D2 * D2) return;
    int k = i >> 9, n = i & 511;
    float v = W[i];
    __nv_bfloat16 h = __float2bfloat16(v);
    __nv_bfloat16 l = __float2bfloat16(v - __bfloat162float(h));
    __nv_bfloat16* row = Bt + (size_t)n * K3;
    row[k] = h; row[512 + k] = l; row[1024 + k] = h;
}

// ---------------- fp32 tiled SGEMM (layer 1 + classifier) ------------------
__global__ void __launch_bounds__(256)
sgemm_kernel(const float* __restrict__ A, const float* __restrict__ B,
             float* __restrict__ C, int M, int N, int K,
             const float* __restrict__ bias)
{
    __shared__ float As[16][128];
    __shared__ float Bs[16][128];
    const int tid = threadIdx.x;
    const int tx = tid & 15, ty = tid >> 4;
    const int row0 = blockIdx.y * 128, col0 = blockIdx.x * 128;
    float acc[8][8];
#pragma unroll
    for (int i = 0; i < 8; i++)
#pragma unroll
        for (int j = 0; j < 8; j++) acc[i][j] = 0.f;
    const int a_r = tid >> 1, a_c = (tid & 1) * 8;
    const int b_r = tid >> 5, b_c = (tid & 31) * 4;
    for (int k0 = 0; k0 < K; k0 += 16) {
#pragma unroll
        for (int i = 0; i < 8; i++) {
            int kk = k0 + a_c + i;
            float v = 0.f;
            if (row0 + a_r < M && kk < K) v = A[(size_t)(row0 + a_r) * K + kk];
            As[a_c + i][a_r] = v;
        }
#pragma unroll
        for (int i = 0; i < 2; i++) {
            int kk = k0 + b_r + i * 8;
#pragma unroll
            for (int j = 0; j < 4; j++) {
                int cc = col0 + b_c + j;
                float v = 0.f;
                if (kk < K && cc < N) v = B[(size_t)kk * N + cc];
                Bs[b_r + i * 8][b_c + j] = v;
            }
        }
        __syncthreads();
#pragma unroll
        for (int kk = 0; kk < 16; kk++) {
            float a[8], b[8];
#pragma unroll
            for (int i = 0; i < 4; i++) {
                a[i] = As[kk][ty * 4 + i];
                a[4 + i] = As[kk][64 + ty * 4 + i];
            }
#pragma unroll
            for (int j = 0; j < 4; j++) {
                b[j] = Bs[kk][tx * 4 + j];
                b[4 + j] = Bs[kk][64 + tx * 4 + j];
            }
#pragma unroll
            for (int i = 0; i < 8; i++)
#pragma unroll
                for (int j = 0; j < 8; j++)
                    acc[i][j] = fmaf(a[i], b[j], acc[i][j]);
        }
        __syncthreads();
    }
#pragma unroll
    for (int i = 0; i < 8; i++) {
        int r = row0 + ((i < 4) ? (ty * 4 + i) : (64 + ty * 4 + (i - 4)));
        if (r >= M) continue;
#pragma unroll
        for (int j = 0; j < 8; j++) {
            int c = col0 + ((j < 4) ? (tx * 4 + j) : (64 + tx * 4 + (j - 4)));
            if (c < N) C[(size_t)r * N + c] = acc[i][j] + (bias ? bias[c] : 0.f);
        }
    }
}

// =================== CSR build (once per launch) ===========================
__global__ void init_deg_kernel(int* deg) {
    int i = blockIdx.x * blockDim.x + threadIdx.x;
    if (i < N_NODES) deg[i] = 1;               // implicit self loop
}
__global__ void hist_kernel(const int* __restrict__ ei, int E, int* deg) {
    int i = blockIdx.x * blockDim.x + threadIdx.x;
    if (i < E) atomicAdd(&deg[ei[(size_t)E + i]], 1);
}
// single-block inclusive scan over 50000 ints (chunked Hillis-Steele)
__global__ void scan_kernel(const int* __restrict__ deg, int* __restrict__ off)
{
    __shared__ int sh[1024];
    __shared__ int carry;
    if (threadIdx.x == 0) carry = 0;
    __syncthreads();
    for (int base = 0; base < N_NODES; base += 1024) {
        int i = base + threadIdx.x;
        int v = (i < N_NODES) ? deg[i] : 0;
        sh[threadIdx.x] = v;
        __syncthreads();
#pragma unroll
        for (int d = 1; d < 1024; d <<= 1) {
            int t = (threadIdx.x >= d) ? sh[threadIdx.x - d] : 0;
            __syncthreads();
            sh[threadIdx.x] += t;
            __syncthreads();
        }
        int incl = sh[threadIdx.x] + carry;
        if (i < N_NODES) off[i + 1] = incl;
        __syncthreads();
        if (threadIdx.x == 1023) carry = incl;
        __syncthreads();
    }
    if (threadIdx.x == 0) off[0] = 0;
}
__global__ void copy_off_kernel(const int* __restrict__ off, int* __restrict__ cur) {
    int i = blockIdx.x * blockDim.x + threadIdx.x;
    if (i < N_NODES) cur[i] = off[i];
}
__global__ void scatter_kernel(const int* __restrict__ ei, int E, int ET,
                               int* __restrict__ cur, int* __restrict__ csr)
{
    int i = blockIdx.x * blockDim.x + threadIdx.x;
    if (i >= ET) return;
    int src, dst;
    if (i < E) { src = ei[i]; dst = ei[(size_t)E + i]; }
    else       { src = dst = i - E; }
    int pos = atomicAdd(&cur[dst], 1);
    csr[pos] = src;
}

// ============ fused GAT edge layer: one warp per destination node ==========
// out[dst] = elu( (sum_e exp(att . lrelu(xl[src]+xr[dst])) * xl[src]) / denom + bias )
__global__ void __launch_bounds__(256)
gat_edge_fused_kernel(const float* __restrict__ xl,
                      const float* __restrict__ xr,
                      const int* __restrict__ off,
                      const int* __restrict__ csr,
                      const float* __restrict__ att,
                      const float* __restrict__ bias,
                      float* __restrict__ out)
{
    const int wid  = threadIdx.x >> 5;
    const int lane = threadIdx.x & 31;
    const int node = blockIdx.x * 8 + wid;
    if (node >= N_NODES) return;

    const float4* at4 = (const float4*)att;
    const float4* xr4 = (const float4*)(xr + (size_t)node * D2);
    const float4* b4  = (const float4*)bias;

    float4 attf[HEADS], xrf[HEADS], accf[HEADS];
    float  den[HEADS];
#pragma unroll
    for (int h = 0; h < HEADS; h++) {
        attf[h] = at4[h * 32 + lane];
        xrf[h]  = xr4[h * 32 + lane];
        accf[h] = make_float4(0.f, 0.f, 0.f, 0.f);
        den[h]  = 0.f;
    }

    const int s = off[node], e = off[node + 1];
    for (int i = s; i < e; i++) {
        int src = csr[i];
        const float4* xl4 = (const float4*)(xl + (size_t)src * D2);
        float4 xlf[HEADS];
        float  lg[HEADS];
#pragma unroll
        for (int h = 0; h < HEADS; h++) {
            float4 v = xl4[h * 32 + lane];
            xlf[h] = v;
            float ax = v.x + xrf[h].x; ax = ax > 0.f ? ax : NEG * ax;
            float ay = v.y + xrf[h].y; ay = ay > 0.f ? ay : NEG * ay;
            float az = v.z + xrf[h].z; az = az > 0.f ? az : NEG * az;
            float aw = v.w + xrf[h].w; aw = aw > 0.f ? aw : NEG * aw;
            lg[h] = ax * attf[h].x + ay * attf[h].y + az * attf[h].z + aw * attf[h].w;
        }
#pragma unroll
        for (int o = 16; o > 0; o >>= 1)
#pragma unroll
            for (int h = 0; h < HEADS; h++)
                lg[h] += __shfl_xor_sync(0xffffffffu, lg[h], o);
#pragma unroll
        for (int h = 0; h < HEADS; h++) {
            float pv = __expf(lg[h]);
            den[h] += pv;
            accf[h].x = fmaf(pv, xlf[h].x, accf[h].x);
            accf[h].y = fmaf(pv, xlf[h].y, accf[h].y);
            accf[h].z = fmaf(pv, xlf[h].z, accf[h].z);
            accf[h].w = fmaf(pv, xlf[h].w, accf[h].w);
        }
    }

    float4* o4 = (float4*)(out + (size_t)node * D2);
#pragma unroll
    for (int h = 0; h < HEADS; h++) {
        float4 bb = b4[h * 32 + lane];
        float  r  = 1.f / den[h];
        float ox = fmaf(accf[h].x, r, bb.x); ox = ox > 0.f ? ox : expm1f(ox);
        float oy = fmaf(accf[h].y, r, bb.y); oy = oy > 0.f ? oy : expm1f(oy);
        float oz = fmaf(accf[h].z, r, bb.z); oz = oz > 0.f ? oz : expm1f(oz);
        float ow = fmaf(accf[h].w, r, bb.w); ow = ow > 0.f ? ow : expm1f(ow);
        o4[h * 32 + lane] = make_float4(ox, oy, oz, ow);
    }
}

// ---------------- host orchestration ---------------------------------------
extern "C" void kernel_launch(void* const* d_in, const int* in_sizes, int n_in,
                              void* d_out, int out_size)
{
    const float* x    = (const float*)d_in[0];
    const int*   ei   = (const int*)d_in[1];
    const float* W1l  = (const float*)d_in[2];
    const float* W1r  = (const float*)d_in[3];
    const float* att1 = (const float*)d_in[4];
    const float* b1   = (const float*)d_in[5];
    const float* W2l  = (const float*)d_in[6];
    const float* W2r  = (const float*)d_in[7];
    const float* att2 = (const float*)d_in[8];
    const float* b2   = (const float*)d_in[9];
    const float* Wc   = (const float*)d_in[10];
    const float* bc   = (const float*)d_in[11];

    const int E    = in_sizes[1] / 2;
    const int ET   = E + N_NODES;
    const int K_in = in_sizes[0] / N_NODES;   // 55

    float *bufA, *bufB, *xl, *xr;
    __nv_bfloat16 *a2, *btl, *btr;
    int *deg, *off, *cur, *csr;
    cudaGetSymbolAddress((void**)&bufA, g_bufA);
    cudaGetSymbolAddress((void**)&bufB, g_bufB);
    cudaGetSymbolAddress((void**)&xl,   g_xl);
    cudaGetSymbolAddress((void**)&xr,   g_xr);
    cudaGetSymbolAddress((void**)&a2,   g_a2);
    cudaGetSymbolAddress((void**)&btl,  g_btl);
    cudaGetSymbolAddress((void**)&btr,  g_btr);
    cudaGetSymbolAddress((void**)&deg,  g_deg);
    cudaGetSymbolAddress((void**)&off,  g_off);
    cudaGetSymbolAddress((void**)&cur,  g_cur);
    cudaGetSymbolAddress((void**)&csr,  g_csr);

    cudaFuncSetAttribute(mma_gemm_kernel,
                         cudaFuncAttributeMaxDynamicSharedMemorySize, 65536);

    // ---- CSR build (dst-grouped edges, reused by all 3 layers) ----
    init_deg_kernel<<<(N_NODES + 255) / 256, 256>>>(deg);
    hist_kernel<<<(E + 255) / 256, 256>>>(ei, E, deg);
    scan_kernel<<<1, 1024>>>(deg, off);
    copy_off_kernel<<<(N_NODES + 255) / 256, 256>>>(off, cur);
    scatter_kernel<<<(ET + 255) / 256, 256>>>(ei, E, ET, cur, csr);

    // W2 split conversion (used by layers 2 and 3)
    cvt_wt_kernel<<<(D2 * D2 + 255) / 256, 256>>>(W2l, btl);
    cvt_wt_kernel<<<(D2 * D2 + 255) / 256, 256>>>(W2r, btr);

    const int ngrid = (N_NODES + 7) / 8;

    // ---- layer 1 (K=55, SIMT GEMMs) -> bufB ----
    {
        dim3 gg(D2 / 128, (N_NODES + 127) / 128);
        sgemm_kernel<<<gg, 256>>>(x, W1l, xl, N_NODES, D2, K_in, nullptr);
        sgemm_kernel<<<gg, 256>>>(x, W1r, xr, N_NODES, D2, K_in, nullptr);
        gat_edge_fused_kernel<<<ngrid, 256>>>(xl, xr, off, csr, att1, b1, bufB);
    }

    // ---- layers 2 & 3 (tensor-core GEMMs via mma.sync) ----
    const int cvt_total = M_PAD * D2;
    dim3 tg(D2 / 128, M_PAD / 128);   // (4, 391)

    // layer 2: bufB -> bufA
    cvt_act_kernel<<<(cvt_total + 255) / 256, 256>>>(bufB, a2, cvt_total);
    mma_gemm_kernel<<<tg, 256, 65536>>>(a2, btl, xl);
    mma_gemm_kernel<<<tg, 256, 65536>>>(a2, btr, xr);
    gat_edge_fused_kernel<<<ngrid, 256>>>(xl, xr, off, csr, att2, b2, bufA);

    // layer 3 (conv2 again): bufA -> bufB
    cvt_act_kernel<<<(cvt_total + 255) / 256, 256>>>(bufA, a2, cvt_total);
    mma_gemm_kernel<<<tg, 256, 65536>>>(a2, btl, xl);
    mma_gemm_kernel<<<tg, 256, 65536>>>(a2, btr, xr);
    gat_edge_fused_kernel<<<ngrid, 256>>>(xl, xr, off, csr, att2, b2, bufB);

    // classifier: d_out = bufB @ Wc + bc   (N = 49)
    dim3 gc(1, (N_NODES + 127) / 128);
    sgemm_kernel<<<gc, 256>>>(bufB, Wc, (float*)d_out, N_NODES, 49, D2, bc);
}

// round 11
// speedup vs baseline: 2.8283x; 1.1580x over previous
#include <cuda_runtime.h>
#include <cuda_bf16.h>
#include <math.h>
#include <stdint.h>

#define N_NODES 50000
#define M_PAD   50048          // 391 * 128
#define D2      512
#define HEADS   4
#define NEG     0.2f
#define MAXE    450048
#define BK      64             // bf16 K-elems per smem stage (128B rows, SW128)
#define K3      1536           // 3*512  (hi|hi|lo split, layers 2/3 + classifier)
#define K1      192            // 3*64   (layer 1, K=55 padded to 64)

// ---------------- scratch (static device globals; zero-initialized) -------
__device__ __align__(128) float g_xl  [(size_t)M_PAD * D2];
__device__ __align__(128) float g_xr  [(size_t)M_PAD * D2];
__device__ __align__(128) __nv_bfloat16 g_a2  [(size_t)M_PAD * K3];  // act split (layers 2/3 in, classifier in)
__device__ __align__(128) __nv_bfloat16 g_ax2 [(size_t)M_PAD * K1];  // x split (layer 1 A)
__device__ __align__(128) __nv_bfloat16 g_btl [(size_t)D2 * K3];     // W2l split
__device__ __align__(128) __nv_bfloat16 g_btr [(size_t)D2 * K3];     // W2r split
__device__ __align__(128) __nv_bfloat16 g_bw1l[(size_t)D2 * K1];     // W1l split
__device__ __align__(128) __nv_bfloat16 g_bw1r[(size_t)D2 * K1];     // W1r split
__device__ __align__(128) __nv_bfloat16 g_btc [(size_t)128 * K3];    // Wc split (49 -> 128 rows)
__device__ int g_deg[N_NODES];
__device__ int g_off[N_NODES + 1];
__device__ int g_cur[N_NODES];
__device__ int g_csr[MAXE];

// ======================= helpers ===========================================
__device__ __forceinline__ uint32_t smem_u32(const void* p) {
    uint32_t a;
    asm("{ .reg .u64 t; cvta.to.shared.u64 t, %1; cvt.u32.u64 %0, t; }"
        : "=r"(a) : "l"(p));
    return a;
}
__device__ __forceinline__ uint32_t lds32(uint32_t addr) {
    uint32_t v;
    asm volatile("ld.shared.b32 %0, [%1];" : "=r"(v) : "r"(addr));
    return v;
}
__device__ __forceinline__ uint32_t tile_addr(int r, int kb) {
    return (uint32_t)(r * 128 + ((((kb >> 4) ^ (r & 7))) << 4) + (kb & 15));
}
#define SW128(o) ((o) ^ (((o) >> 3) & 0x70))

__device__ __forceinline__ void mma16816(float* c, const uint32_t* a, const uint32_t* b) {
    asm volatile(
        "mma.sync.aligned.m16n8k16.row.col.f32.bf16.bf16.f32 "
        "{%0,%1,%2,%3}, {%4,%5,%6,%7}, {%8,%9}, {%0,%1,%2,%3};"
        : "+f"(c[0]), "+f"(c[1]), "+f"(c[2]), "+f"(c[3])
        : "r"(a[0]), "r"(a[1]), "r"(a[2]), "r"(a[3]), "r"(b[0]), "r"(b[1]));
}

// ================= mma.sync GEMM: C = A'[.,KTOT] @ B'[.,KTOT]^T ============
// 128x128 CTA tile, 8 warps (2x4), warp tile 64x32, BK=64 double-buffered
// cp.async (SW128). If bias != null: bounded, bias-adding epilogue
// (ldc doubles as the output column count).
template <int KTOT>
__device__ __forceinline__ void load_tile(uint32_t sdst, const __nv_bfloat16* __restrict__ g,
                                          size_t row0, int k0) {
    const char* gb = (const char*)g + (row0 * (size_t)KTOT + (size_t)k0) * 2;
#pragma unroll
    for (int i = 0; i < 4; i++) {
        int c = threadIdx.x + i * 256;       // 1024 16B chunks
        int r = c >> 3;
        int o = (c & 7) * 16;
        uint32_t dst = sdst + SW128((uint32_t)(r * 128 + o));
        asm volatile("cp.async.cg.shared.global [%0], [%1], 16;"
                     :: "r"(dst), "l"(gb + (size_t)r * (KTOT * 2) + o) : "memory");
    }
}

template <int KTOT>
__global__ void __launch_bounds__(256, 2)
mma_gemm_kernel(const __nv_bfloat16* __restrict__ A2,
                const __nv_bfloat16* __restrict__ Bt,
                float* __restrict__ C, int ldc, int mrows,
                const float* __restrict__ bias)
{
    constexpr int NSTG = KTOT / BK;
    extern __shared__ char dsm[];            // 2 stages x (16KB A + 16KB B) = 64KB
    const int tid    = threadIdx.x;
    const int wid    = tid >> 5;
    const int lane   = tid & 31;
    const int warp_m = wid >> 2;
    const int warp_n = wid & 3;
    const int gID    = lane >> 2;
    const int l4     = lane & 3;
    const size_t m0  = (size_t)blockIdx.y * 128;
    const int    n0  = blockIdx.x * 128;
    const uint32_t smb = smem_u32(dsm);

    float acc[4][4][4];
#pragma unroll
    for (int i = 0; i < 4; i++)
#pragma unroll
        for (int j = 0; j < 4; j++)
#pragma unroll
            for (int q = 0; q < 4; q++) acc[i][j][q] = 0.f;

    load_tile<KTOT>(smb,                 A2, m0, 0);
    load_tile<KTOT>(smb + 16384,         Bt, (size_t)n0, 0);
    asm volatile("cp.async.commit_group;" ::: "memory");
    load_tile<KTOT>(smb + 32768,         A2, m0, BK);
    load_tile<KTOT>(smb + 32768 + 16384, Bt, (size_t)n0, BK);
    asm volatile("cp.async.commit_group;" ::: "memory");

    for (int s = 0; s < NSTG; s++) {
        if (s < NSTG - 1) asm volatile("cp.async.wait_group 1;" ::: "memory");
        else              asm volatile("cp.async.wait_group 0;" ::: "memory");
        __syncthreads();

        const int b = s & 1;
        const uint32_t As = smb + b * 32768;
        const uint32_t Bs = As + 16384;

#pragma unroll
        for (int ks = 0; ks < 4; ks++) {
            const int kb = ks * 32 + l4 * 4;
            uint32_t a[4][4], bb[4][2];
#pragma unroll
            for (int mf = 0; mf < 4; mf++) {
                int r0 = warp_m * 64 + mf * 16 + gID;
                a[mf][0] = lds32(As + tile_addr(r0,     kb));
                a[mf][1] = lds32(As + tile_addr(r0 + 8, kb));
                a[mf][2] = lds32(As + tile_addr(r0,     kb + 16));
                a[mf][3] = lds32(As + tile_addr(r0 + 8, kb + 16));
            }
#pragma unroll
            for (int nf = 0; nf < 4; nf++) {
                int nr = warp_n * 32 + nf * 8 + gID;
                bb[nf][0] = lds32(Bs + tile_addr(nr, kb));
                bb[nf][1] = lds32(Bs + tile_addr(nr, kb + 16));
            }
#pragma unroll
            for (int mf = 0; mf < 4; mf++)
#pragma unroll
                for (int nf = 0; nf < 4; nf++)
                    mma16816(acc[mf][nf], a[mf], bb[nf]);
        }
        __syncthreads();

        const int t = s + 2;
        if (t < NSTG) {
            load_tile<KTOT>(smb + b * 32768,         A2, m0, t * BK);
            load_tile<KTOT>(smb + b * 32768 + 16384, Bt, (size_t)n0, t * BK);
            asm volatile("cp.async.commit_group;" ::: "memory");
        }
    }

    if (bias == nullptr) {
        // fast path: full tile in-bounds columns, stride ldc
        float* Cbase = C + m0 * (size_t)ldc + n0;
#pragma unroll
        for (int mf = 0; mf < 4; mf++) {
            int rr = warp_m * 64 + mf * 16 + gID;
#pragma unroll
            for (int nf = 0; nf < 4; nf++) {
                int cc = warp_n * 32 + nf * 8 + l4 * 2;
                if (m0 + rr < (size_t)mrows)
                    *(float2*)(Cbase + (size_t)rr * ldc + cc) =
                        make_float2(acc[mf][nf][0], acc[mf][nf][1]);
                if (m0 + rr + 8 < (size_t)mrows)
                    *(float2*)(Cbase + (size_t)(rr + 8) * ldc + cc) =
                        make_float2(acc[mf][nf][2], acc[mf][nf][3]);
            }
        }
    } else {
        // bounded path (classifier): ldc == number of valid output columns
#pragma unroll
        for (int mf = 0; mf < 4; mf++) {
            size_t r0g = m0 + warp_m * 64 + mf * 16 + gID;
#pragma unroll
            for (int nf = 0; nf < 4; nf++) {
                int gcol = n0 + warp_n * 32 + nf * 8 + l4 * 2;
#pragma unroll
                for (int q = 0; q < 2; q++) {
                    int c = gcol + q;
                    if (c >= ldc) continue;
                    float bv = bias[c];
                    if (r0g < (size_t)mrows)
                        C[r0g * ldc + c] = acc[mf][nf][q] + bv;
                    if (r0g + 8 < (size_t)mrows)
                        C[(r0g + 8) * ldc + c] = acc[mf][nf][2 + q] + bv;
                }
            }
        }
    }
}

// ---------------- one-time weight / input splits ---------------------------
__global__ void cvt_w2_kernel(const float* __restrict__ W,   // [512][512]
                              __nv_bfloat16* __restrict__ Bt) // [512][K3]
{
    int i = blockIdx.x * blockDim.x + threadIdx.x;
    if (i >= D2 * D2) return;
    int k = i >> 9, n = i & 511;
    float v = W[i];
    __nv_bfloat16 h = __float2bfloat16(v);
    __nv_bfloat16 l = __float2bfloat16(v - __bfloat162float(h));
    __nv_bfloat16* row = Bt + (size_t)n * K3;
    row[k] = h; row[512 + k] = l; row[1024 + k] = h;
}
__global__ void cvt_w1_kernel(const float* __restrict__ W,   // [55][512]
                              __nv_bfloat16* __restrict__ Bt, // [512][K1]
                              int Kin)
{
    int i = blockIdx.x * blockDim.x + threadIdx.x;
    if (i >= D2 * 64) return;
    int kk = i >> 9, n = i & 511;
    float v = (kk < Kin) ? W[(size_t)kk * D2 + n] : 0.f;
    __nv_bfloat16 h = __float2bfloat16(v);
    __nv_bfloat16 l = __float2bfloat16(v - __bfloat162float(h));
    __nv_bfloat16* row = Bt + (size_t)n * K1;
    row[kk] = h; row[64 + kk] = l; row[128 + kk] = h;
}
__global__ void cvt_x_kernel(const float* __restrict__ x,    // [N_NODES][55]
                             __nv_bfloat16* __restrict__ A2, // [M_PAD][K1]
                             int Kin)
{
    int i = blockIdx.x * blockDim.x + threadIdx.x;
    if (i >= M_PAD * 64) return;
    int m = i >> 6, k = i & 63;
    float v = (m < N_NODES && k < Kin) ? x[(size_t)m * Kin + k] : 0.f;
    __nv_bfloat16 h = __float2bfloat16(v);
    __nv_bfloat16 l = __float2bfloat16(v - __bfloat162float(h));
    __nv_bfloat16* row = A2 + (size_t)m * K1;
    row[k] = h; row[64 + k] = h; row[128 + k] = l;
}
__global__ void cvt_wc_kernel(const float* __restrict__ Wc,  // [512][49]
                              __nv_bfloat16* __restrict__ Bt) // [128][K3]
{
    int i = blockIdx.x * blockDim.x + threadIdx.x;
    if (i >= 128 * D2) return;
    int k = i >> 7, n = i & 127;
    float v = (n < 49) ? Wc[(size_t)k * 49 + n] : 0.f;
    __nv_bfloat16 h = __float2bfloat16(v);
    __nv_bfloat16 l = __float2bfloat16(v - __bfloat162float(h));
    __nv_bfloat16* row = Bt + (size_t)n * K3;
    row[k] = h; row[512 + k] = l; row[1024 + k] = h;
}

// =================== CSR build (once per launch) ===========================
__global__ void init_deg_kernel(int* deg) {
    int i = blockIdx.x * blockDim.x + threadIdx.x;
    if (i < N_NODES) deg[i] = 1;               // implicit self loop
}
__global__ void hist_kernel(const int* __restrict__ ei, int E, int* deg) {
    int i = blockIdx.x * blockDim.x + threadIdx.x;
    if (i < E) atomicAdd(&deg[ei[(size_t)E + i]], 1);
}
__global__ void scan_kernel(const int* __restrict__ deg, int* __restrict__ off)
{
    __shared__ int sh[1024];
    __shared__ int carry;
    if (threadIdx.x == 0) carry = 0;
    __syncthreads();
    for (int base = 0; base < N_NODES; base += 1024) {
        int i = base + threadIdx.x;
        int v = (i < N_NODES) ? deg[i] : 0;
        sh[threadIdx.x] = v;
        __syncthreads();
#pragma unroll
        for (int d = 1; d < 1024; d <<= 1) {
            int t = (threadIdx.x >= d) ? sh[threadIdx.x - d] : 0;
            __syncthreads();
            sh[threadIdx.x] += t;
            __syncthreads();
        }
        int incl = sh[threadIdx.x] + carry;
        if (i < N_NODES) off[i + 1] = incl;
        __syncthreads();
        if (threadIdx.x == 1023) carry = incl;
        __syncthreads();
    }
    if (threadIdx.x == 0) off[0] = 0;
}
__global__ void copy_off_kernel(const int* __restrict__ off, int* __restrict__ cur) {
    int i = blockIdx.x * blockDim.x + threadIdx.x;
    if (i < N_NODES) cur[i] = off[i];
}
__global__ void scatter_kernel(const int* __restrict__ ei, int E, int ET,
                               int* __restrict__ cur, int* __restrict__ csr)
{
    int i = blockIdx.x * blockDim.x + threadIdx.x;
    if (i >= ET) return;
    int src, dst;
    if (i < E) { src = ei[i]; dst = ei[(size_t)E + i]; }
    else       { src = dst = i - E; }
    int pos = atomicAdd(&cur[dst], 1);
    csr[pos] = src;
}

// ============ fused GAT edge layer: one warp per destination node ==========
// a2[dst] = split( elu( (sum_e exp(att.lrelu(xl[src]+xr[dst])) * xl[src]) / denom + bias ) )
__global__ void __launch_bounds__(256)
gat_edge_fused_kernel(const float* __restrict__ xl,
                      const float* __restrict__ xr,
                      const int* __restrict__ off,
                      const int* __restrict__ csr,
                      const float* __restrict__ att,
                      const float* __restrict__ bias,
                      __nv_bfloat16* __restrict__ a2)
{
    const int wid  = threadIdx.x >> 5;
    const int lane = threadIdx.x & 31;
    const int node = blockIdx.x * 8 + wid;
    if (node >= N_NODES) return;

    const float4* at4 = (const float4*)att;
    const float4* xr4 = (const float4*)(xr + (size_t)node * D2);
    const float4* b4  = (const float4*)bias;

    float4 attf[HEADS], xrf[HEADS], accf[HEADS];
    float  den[HEADS];
#pragma unroll
    for (int h = 0; h < HEADS; h++) {
        attf[h] = at4[h * 32 + lane];
        xrf[h]  = xr4[h * 32 + lane];
        accf[h] = make_float4(0.f, 0.f, 0.f, 0.f);
        den[h]  = 0.f;
    }

    const int s = off[node], e = off[node + 1];
    for (int i = s; i < e; i++) {
        int src = csr[i];
        const float4* xl4 = (const float4*)(xl + (size_t)src * D2);
        float4 xlf[HEADS];
        float  lg[HEADS];
#pragma unroll
        for (int h = 0; h < HEADS; h++) {
            float4 v = xl4[h * 32 + lane];
            xlf[h] = v;
            float ax = v.x + xrf[h].x; ax = ax > 0.f ? ax : NEG * ax;
            float ay = v.y + xrf[h].y; ay = ay > 0.f ? ay : NEG * ay;
            float az = v.z + xrf[h].z; az = az > 0.f ? az : NEG * az;
            float aw = v.w + xrf[h].w; aw = aw > 0.f ? aw : NEG * aw;
            lg[h] = ax * attf[h].x + ay * attf[h].y + az * attf[h].z + aw * attf[h].w;
        }
#pragma unroll
        for (int o = 16; o > 0; o >>= 1)
#pragma unroll
            for (int h = 0; h < HEADS; h++)
                lg[h] += __shfl_xor_sync(0xffffffffu, lg[h], o);
#pragma unroll
        for (int h = 0; h < HEADS; h++) {
            float pv = __expf(lg[h]);
            den[h] += pv;
            accf[h].x = fmaf(pv, xlf[h].x, accf[h].x);
            accf[h].y = fmaf(pv, xlf[h].y, accf[h].y);
            accf[h].z = fmaf(pv, xlf[h].z, accf[h].z);
            accf[h].w = fmaf(pv, xlf[h].w, accf[h].w);
        }
    }

    __nv_bfloat16* arow = a2 + (size_t)node * K3;
#pragma unroll
    for (int h = 0; h < HEADS; h++) {
        float4 bb = b4[h * 32 + lane];
        float  r  = 1.f / den[h];
        float ox = fmaf(accf[h].x, r, bb.x); ox = ox > 0.f ? ox : expm1f(ox);
        float oy = fmaf(accf[h].y, r, bb.y); oy = oy > 0.f ? oy : expm1f(oy);
        float oz = fmaf(accf[h].z, r, bb.z); oz = oz > 0.f ? oz : expm1f(oz);
        float ow = fmaf(accf[h].w, r, bb.w); ow = ow > 0.f ? ow : expm1f(ow);

        __nv_bfloat16 h0 = __float2bfloat16(ox), h1 = __float2bfloat16(oy);
        __nv_bfloat16 h2 = __float2bfloat16(oz), h3 = __float2bfloat16(ow);
        __nv_bfloat16 l0 = __float2bfloat16(ox - __bfloat162float(h0));
        __nv_bfloat16 l1 = __float2bfloat16(oy - __bfloat162float(h1));
        __nv_bfloat16 l2 = __float2bfloat16(oz - __bfloat162float(h2));
        __nv_bfloat16 l3 = __float2bfloat16(ow - __bfloat162float(h3));

        __nv_bfloat162 hp0 = __halves2bfloat162(h0, h1);
        __nv_bfloat162 hp1 = __halves2bfloat162(h2, h3);
        __nv_bfloat162 lp0 = __halves2bfloat162(l0, l1);
        __nv_bfloat162 lp1 = __halves2bfloat162(l2, l3);
        uint2 hv, lv;
        memcpy(&hv.x, &hp0, 4); memcpy(&hv.y, &hp1, 4);
        memcpy(&lv.x, &lp0, 4); memcpy(&lv.y, &lp1, 4);

        int k = h * 128 + lane * 4;
        *(uint2*)(arow + k)        = hv;
        *(uint2*)(arow + 512 + k)  = hv;
        *(uint2*)(arow + 1024 + k) = lv;
    }
}

// ---------------- host orchestration ---------------------------------------
extern "C" void kernel_launch(void* const* d_in, const int* in_sizes, int n_in,
                              void* d_out, int out_size)
{
    const float* x    = (const float*)d_in[0];
    const int*   ei   = (const int*)d_in[1];
    const float* W1l  = (const float*)d_in[2];
    const float* W1r  = (const float*)d_in[3];
    const float* att1 = (const float*)d_in[4];
    const float* b1   = (const float*)d_in[5];
    const float* W2l  = (const float*)d_in[6];
    const float* W2r  = (const float*)d_in[7];
    const float* att2 = (const float*)d_in[8];
    const float* b2   = (const float*)d_in[9];
    const float* Wc   = (const float*)d_in[10];
    const float* bc   = (const float*)d_in[11];

    const int E    = in_sizes[1] / 2;
    const int ET   = E + N_NODES;
    const int K_in = in_sizes[0] / N_NODES;   // 55

    float *xl, *xr;
    __nv_bfloat16 *a2, *ax2, *btl, *btr, *bw1l, *bw1r, *btc;
    int *deg, *off, *cur, *csr;
    cudaGetSymbolAddress((void**)&xl,   g_xl);
    cudaGetSymbolAddress((void**)&xr,   g_xr);
    cudaGetSymbolAddress((void**)&a2,   g_a2);
    cudaGetSymbolAddress((void**)&ax2,  g_ax2);
    cudaGetSymbolAddress((void**)&btl,  g_btl);
    cudaGetSymbolAddress((void**)&btr,  g_btr);
    cudaGetSymbolAddress((void**)&bw1l, g_bw1l);
    cudaGetSymbolAddress((void**)&bw1r, g_bw1r);
    cudaGetSymbolAddress((void**)&btc,  g_btc);
    cudaGetSymbolAddress((void**)&deg,  g_deg);
    cudaGetSymbolAddress((void**)&off,  g_off);
    cudaGetSymbolAddress((void**)&cur,  g_cur);
    cudaGetSymbolAddress((void**)&csr,  g_csr);

    cudaFuncSetAttribute(mma_gemm_kernel<K3>,
                         cudaFuncAttributeMaxDynamicSharedMemorySize, 65536);
    cudaFuncSetAttribute(mma_gemm_kernel<K1>,
                         cudaFuncAttributeMaxDynamicSharedMemorySize, 65536);

    // ---- CSR build (dst-grouped edges, reused by all 3 layers) ----
    init_deg_kernel<<<(N_NODES + 255) / 256, 256>>>(deg);
    hist_kernel<<<(E + 255) / 256, 256>>>(ei, E, deg);
    scan_kernel<<<1, 1024>>>(deg, off);
    copy_off_kernel<<<(N_NODES + 255) / 256, 256>>>(off, cur);
    scatter_kernel<<<(ET + 255) / 256, 256>>>(ei, E, ET, cur, csr);

    // ---- one-time splits ----
    cvt_w2_kernel<<<(D2 * D2 + 255) / 256, 256>>>(W2l, btl);
    cvt_w2_kernel<<<(D2 * D2 + 255) / 256, 256>>>(W2r, btr);
    cvt_w1_kernel<<<(D2 * 64 + 255) / 256, 256>>>(W1l, bw1l, K_in);
    cvt_w1_kernel<<<(D2 * 64 + 255) / 256, 256>>>(W1r, bw1r, K_in);
    cvt_x_kernel<<<(M_PAD * 64 + 255) / 256, 256>>>(x, ax2, K_in);
    cvt_wc_kernel<<<(128 * D2 + 255) / 256, 256>>>(Wc, btc);

    const int ngrid = (N_NODES + 7) / 8;
    dim3 tg(D2 / 128, M_PAD / 128);   // (4, 391)

    // ---- layer 1 ----
    mma_gemm_kernel<K1><<<tg, 256, 65536>>>(ax2, bw1l, xl, D2, M_PAD, nullptr);
    mma_gemm_kernel<K1><<<tg, 256, 65536>>>(ax2, bw1r, xr, D2, M_PAD, nullptr);
    gat_edge_fused_kernel<<<ngrid, 256>>>(xl, xr, off, csr, att1, b1, a2);

    // ---- layer 2 ----
    mma_gemm_kernel<K3><<<tg, 256, 65536>>>(a2, btl, xl, D2, M_PAD, nullptr);
    mma_gemm_kernel<K3><<<tg, 256, 65536>>>(a2, btr, xr, D2, M_PAD, nullptr);
    gat_edge_fused_kernel<<<ngrid, 256>>>(xl, xr, off, csr, att2, b2, a2);

    // ---- layer 3 (conv2 again) ----
    mma_gemm_kernel<K3><<<tg, 256, 65536>>>(a2, btl, xl, D2, M_PAD, nullptr);
    mma_gemm_kernel<K3><<<tg, 256, 65536>>>(a2, btr, xr, D2, M_PAD, nullptr);
    gat_edge_fused_kernel<<<ngrid, 256>>>(xl, xr, off, csr, att2, b2, a2);

    // ---- classifier: d_out = h @ Wc + bc  (49 cols, bounded epilogue) ----
    dim3 gc(1, M_PAD / 128);
    mma_gemm_kernel<K3><<<gc, 256, 65536>>>(a2, btc, (float*)d_out, 49, N_NODES, bc);
}

// round 12
// speedup vs baseline: 3.0428x; 1.0758x over previous
#include <cuda_runtime.h>
#include <cuda_bf16.h>
#include <math.h>
#include <stdint.h>

#define N_NODES 50000
#define M_PAD   50048          // 391 * 128
#define D2      512
#define HEADS   4
#define NEG     0.2f
#define MAXE    450048
#define BK      64             // bf16 K-elems per smem stage (128B rows, SW128)
#define K3      1536           // 3*512  (hi|hi|lo split, layers 2/3 + classifier)
#define K1      192            // 3*64   (layer 1, K=55 padded to 64)

// ---------------- scratch (static device globals; zero-initialized) -------
__device__ __align__(128) float g_xl  [(size_t)M_PAD * D2];
__device__ __align__(128) float g_xr  [(size_t)M_PAD * D2];
__device__ __align__(128) __nv_bfloat16 g_a2  [(size_t)M_PAD * K3];  // act split
__device__ __align__(128) __nv_bfloat16 g_ax2 [(size_t)M_PAD * K1];  // x split (layer 1 A)
__device__ __align__(128) __nv_bfloat16 g_btl [(size_t)D2 * K3];     // W2l split
__device__ __align__(128) __nv_bfloat16 g_btr [(size_t)D2 * K3];     // W2r split
__device__ __align__(128) __nv_bfloat16 g_bw1l[(size_t)D2 * K1];     // W1l split
__device__ __align__(128) __nv_bfloat16 g_bw1r[(size_t)D2 * K1];     // W1r split
__device__ __align__(128) __nv_bfloat16 g_btc [(size_t)128 * K3];    // Wc split (49 -> 128 rows)
__device__ int g_deg[N_NODES];
__device__ int g_off[N_NODES + 1];
__device__ int g_cur[N_NODES];
__device__ int g_csr[MAXE];

// ======================= helpers ===========================================
__device__ __forceinline__ uint32_t smem_u32(const void* p) {
    uint32_t a;
    asm("{ .reg .u64 t; cvta.to.shared.u64 t, %1; cvt.u32.u64 %0, t; }"
        : "=r"(a) : "l"(p));
    return a;
}
__device__ __forceinline__ uint32_t lds32(uint32_t addr) {
    uint32_t v;
    asm volatile("ld.shared.b32 %0, [%1];" : "=r"(v) : "r"(addr));
    return v;
}
__device__ __forceinline__ uint32_t tile_addr(int r, int kb) {
    return (uint32_t)(r * 128 + ((((kb >> 4) ^ (r & 7))) << 4) + (kb & 15));
}
#define SW128(o) ((o) ^ (((o) >> 3) & 0x70))

__device__ __forceinline__ void mma16816(float* c, const uint32_t* a, const uint32_t* b) {
    asm volatile(
        "mma.sync.aligned.m16n8k16.row.col.f32.bf16.bf16.f32 "
        "{%0,%1,%2,%3}, {%4,%5,%6,%7}, {%8,%9}, {%0,%1,%2,%3};"
        : "+f"(c[0]), "+f"(c[1]), "+f"(c[2]), "+f"(c[3])
        : "r"(a[0]), "r"(a[1]), "r"(a[2]), "r"(a[3]), "r"(b[0]), "r"(b[1]));
}

// 16KB tile loader: 128 rows x 128 bytes, SW128-swizzled, 256 threads
template <int KTOT>
__device__ __forceinline__ void load_tile(uint32_t sdst, const __nv_bfloat16* __restrict__ g,
                                          size_t row0, int k0) {
    const char* gb = (const char*)g + (row0 * (size_t)KTOT + (size_t)k0) * 2;
#pragma unroll
    for (int i = 0; i < 4; i++) {
        int c = threadIdx.x + i * 256;       // 1024 16B chunks
        int r = c >> 3;
        int o = (c & 7) * 16;
        uint32_t dst = sdst + SW128((uint32_t)(r * 128 + o));
        asm volatile("cp.async.cg.shared.global [%0], [%1], 16;"
                     :: "r"(dst), "l"(gb + (size_t)r * (KTOT * 2) + o) : "memory");
    }
}

// ============ fused dual GEMM: CL = A'.BtL^T, CR = A'.BtR^T ================
// Shares A tiles between the two GEMMs (halves A DRAM traffic + A smem loads).
// 128x128 CTA tile per output, 8 warps (2x4), warp tile 64x32 per output.
// Stage = A(16KB) + BL(16KB) + BR(16KB) = 48KB, double buffered (96KB smem).
template <int KTOT>
__global__ void __launch_bounds__(256, 1)
mma_gemm_dual_kernel(const __nv_bfloat16* __restrict__ A2,
                     const __nv_bfloat16* __restrict__ BtL,
                     const __nv_bfloat16* __restrict__ BtR,
                     float* __restrict__ CL, float* __restrict__ CR)
{
    constexpr int NSTG = KTOT / BK;
    constexpr int STG  = 49152;              // 48KB per stage
    extern __shared__ char dsm[];
    const int tid    = threadIdx.x;
    const int wid    = tid >> 5;
    const int lane   = tid & 31;
    const int warp_m = wid >> 2;
    const int warp_n = wid & 3;
    const int gID    = lane >> 2;
    const int l4     = lane & 3;
    const size_t m0  = (size_t)blockIdx.y * 128;
    const int    n0  = blockIdx.x * 128;
    const uint32_t smb = smem_u32(dsm);

    float accL[4][4][4], accR[4][4][4];
#pragma unroll
    for (int i = 0; i < 4; i++)
#pragma unroll
        for (int j = 0; j < 4; j++)
#pragma unroll
            for (int q = 0; q < 4; q++) { accL[i][j][q] = 0.f; accR[i][j][q] = 0.f; }

    load_tile<KTOT>(smb,                 A2,  m0, 0);
    load_tile<KTOT>(smb + 16384,         BtL, (size_t)n0, 0);
    load_tile<KTOT>(smb + 32768,         BtR, (size_t)n0, 0);
    asm volatile("cp.async.commit_group;" ::: "memory");
    load_tile<KTOT>(smb + STG,           A2,  m0, BK);
    load_tile<KTOT>(smb + STG + 16384,   BtL, (size_t)n0, BK);
    load_tile<KTOT>(smb + STG + 32768,   BtR, (size_t)n0, BK);
    asm volatile("cp.async.commit_group;" ::: "memory");

    for (int s = 0; s < NSTG; s++) {
        if (s < NSTG - 1) asm volatile("cp.async.wait_group 1;" ::: "memory");
        else              asm volatile("cp.async.wait_group 0;" ::: "memory");
        __syncthreads();

        const uint32_t As = smb + (s & 1) * STG;
        const uint32_t BsL = As + 16384;
        const uint32_t BsR = As + 32768;

#pragma unroll
        for (int ks = 0; ks < 4; ks++) {
            const int kb = ks * 32 + l4 * 4;
            uint32_t a[4][4], bl[4][2], br[4][2];
#pragma unroll
            for (int mf = 0; mf < 4; mf++) {
                int r0 = warp_m * 64 + mf * 16 + gID;
                a[mf][0] = lds32(As + tile_addr(r0,     kb));
                a[mf][1] = lds32(As + tile_addr(r0 + 8, kb));
                a[mf][2] = lds32(As + tile_addr(r0,     kb + 16));
                a[mf][3] = lds32(As + tile_addr(r0 + 8, kb + 16));
            }
#pragma unroll
            for (int nf = 0; nf < 4; nf++) {
                int nr = warp_n * 32 + nf * 8 + gID;
                bl[nf][0] = lds32(BsL + tile_addr(nr, kb));
                bl[nf][1] = lds32(BsL + tile_addr(nr, kb + 16));
                br[nf][0] = lds32(BsR + tile_addr(nr, kb));
                br[nf][1] = lds32(BsR + tile_addr(nr, kb + 16));
            }
#pragma unroll
            for (int mf = 0; mf < 4; mf++)
#pragma unroll
                for (int nf = 0; nf < 4; nf++) {
                    mma16816(accL[mf][nf], a[mf], bl[nf]);
                    mma16816(accR[mf][nf], a[mf], br[nf]);
                }
        }
        __syncthreads();

        const int t = s + 2;
        if (t < NSTG) {
            const uint32_t Ps = smb + (s & 1) * STG;
            load_tile<KTOT>(Ps,          A2,  m0, t * BK);
            load_tile<KTOT>(Ps + 16384,  BtL, (size_t)n0, t * BK);
            load_tile<KTOT>(Ps + 32768,  BtR, (size_t)n0, t * BK);
            asm volatile("cp.async.commit_group;" ::: "memory");
        }
    }

    // epilogue: M_PAD is a multiple of 128 -> no bounds checks
    float* CbL = CL + m0 * D2 + n0;
    float* CbR = CR + m0 * D2 + n0;
#pragma unroll
    for (int mf = 0; mf < 4; mf++) {
        int rr = warp_m * 64 + mf * 16 + gID;
#pragma unroll
        for (int nf = 0; nf < 4; nf++) {
            int cc = warp_n * 32 + nf * 8 + l4 * 2;
            *(float2*)(CbL + (size_t)rr * D2 + cc)       = make_float2(accL[mf][nf][0], accL[mf][nf][1]);
            *(float2*)(CbL + (size_t)(rr + 8) * D2 + cc) = make_float2(accL[mf][nf][2], accL[mf][nf][3]);
            *(float2*)(CbR + (size_t)rr * D2 + cc)       = make_float2(accR[mf][nf][0], accR[mf][nf][1]);
            *(float2*)(CbR + (size_t)(rr + 8) * D2 + cc) = make_float2(accR[mf][nf][2], accR[mf][nf][3]);
        }
    }
}

// ============ single GEMM (classifier): bounded + bias epilogue ============
template <int KTOT>
__global__ void __launch_bounds__(256, 2)
mma_gemm_kernel(const __nv_bfloat16* __restrict__ A2,
                const __nv_bfloat16* __restrict__ Bt,
                float* __restrict__ C, int ldc, int mrows,
                const float* __restrict__ bias)
{
    constexpr int NSTG = KTOT / BK;
    extern __shared__ char dsm[];            // 2 stages x 32KB
    const int tid    = threadIdx.x;
    const int wid    = tid >> 5;
    const int lane   = tid & 31;
    const int warp_m = wid >> 2;
    const int warp_n = wid & 3;
    const int gID    = lane >> 2;
    const int l4     = lane & 3;
    const size_t m0  = (size_t)blockIdx.y * 128;
    const int    n0  = blockIdx.x * 128;
    const uint32_t smb = smem_u32(dsm);

    float acc[4][4][4];
#pragma unroll
    for (int i = 0; i < 4; i++)
#pragma unroll
        for (int j = 0; j < 4; j++)
#pragma unroll
            for (int q = 0; q < 4; q++) acc[i][j][q] = 0.f;

    load_tile<KTOT>(smb,                 A2, m0, 0);
    load_tile<KTOT>(smb + 16384,         Bt, (size_t)n0, 0);
    asm volatile("cp.async.commit_group;" ::: "memory");
    load_tile<KTOT>(smb + 32768,         A2, m0, BK);
    load_tile<KTOT>(smb + 32768 + 16384, Bt, (size_t)n0, BK);
    asm volatile("cp.async.commit_group;" ::: "memory");

    for (int s = 0; s < NSTG; s++) {
        if (s < NSTG - 1) asm volatile("cp.async.wait_group 1;" ::: "memory");
        else              asm volatile("cp.async.wait_group 0;" ::: "memory");
        __syncthreads();

        const int b = s & 1;
        const uint32_t As = smb + b * 32768;
        const uint32_t Bs = As + 16384;

#pragma unroll
        for (int ks = 0; ks < 4; ks++) {
            const int kb = ks * 32 + l4 * 4;
            uint32_t a[4][4], bb[4][2];
#pragma unroll
            for (int mf = 0; mf < 4; mf++) {
                int r0 = warp_m * 64 + mf * 16 + gID;
                a[mf][0] = lds32(As + tile_addr(r0,     kb));
                a[mf][1] = lds32(As + tile_addr(r0 + 8, kb));
                a[mf][2] = lds32(As + tile_addr(r0,     kb + 16));
                a[mf][3] = lds32(As + tile_addr(r0 + 8, kb + 16));
            }
#pragma unroll
            for (int nf = 0; nf < 4; nf++) {
                int nr = warp_n * 32 + nf * 8 + gID;
                bb[nf][0] = lds32(Bs + tile_addr(nr, kb));
                bb[nf][1] = lds32(Bs + tile_addr(nr, kb + 16));
            }
#pragma unroll
            for (int mf = 0; mf < 4; mf++)
#pragma unroll
                for (int nf = 0; nf < 4; nf++)
                    mma16816(acc[mf][nf], a[mf], bb[nf]);
        }
        __syncthreads();

        const int t = s + 2;
        if (t < NSTG) {
            load_tile<KTOT>(smb + (s & 1) * 32768,         A2, m0, t * BK);
            load_tile<KTOT>(smb + (s & 1) * 32768 + 16384, Bt, (size_t)n0, t * BK);
            asm volatile("cp.async.commit_group;" ::: "memory");
        }
    }

    // bounded bias epilogue (classifier): ldc == valid output columns
#pragma unroll
    for (int mf = 0; mf < 4; mf++) {
        size_t r0g = m0 + warp_m * 64 + mf * 16 + gID;
#pragma unroll
        for (int nf = 0; nf < 4; nf++) {
            int gcol = n0 + warp_n * 32 + nf * 8 + l4 * 2;
#pragma unroll
            for (int q = 0; q < 2; q++) {
                int c = gcol + q;
                if (c >= ldc) continue;
                float bv = bias[c];
                if (r0g < (size_t)mrows)
                    C[r0g * ldc + c] = acc[mf][nf][q] + bv;
                if (r0g + 8 < (size_t)mrows)
                    C[(r0g + 8) * ldc + c] = acc[mf][nf][2 + q] + bv;
            }
        }
    }
}

// ---------------- one-time weight / input splits ---------------------------
__global__ void cvt_w2_kernel(const float* __restrict__ W,
                              __nv_bfloat16* __restrict__ Bt)
{
    int i = blockIdx.x * blockDim.x + threadIdx.x;
    if (i >= D2 * D2) return;
    int k = i >> 9, n = i & 511;
    float v = W[i];
    __nv_bfloat16 h = __float2bfloat16(v);
    __nv_bfloat16 l = __float2bfloat16(v - __bfloat162float(h));
    __nv_bfloat16* row = Bt + (size_t)n * K3;
    row[k] = h; row[512 + k] = l; row[1024 + k] = h;
}
__global__ void cvt_w1_kernel(const float* __restrict__ W,
                              __nv_bfloat16* __restrict__ Bt, int Kin)
{
    int i = blockIdx.x * blockDim.x + threadIdx.x;
    if (i >= D2 * 64) return;
    int kk = i >> 9, n = i & 511;
    float v = (kk < Kin) ? W[(size_t)kk * D2 + n] : 0.f;
    __nv_bfloat16 h = __float2bfloat16(v);
    __nv_bfloat16 l = __float2bfloat16(v - __bfloat162float(h));
    __nv_bfloat16* row = Bt + (size_t)n * K1;
    row[kk] = h; row[64 + kk] = l; row[128 + kk] = h;
}
__global__ void cvt_x_kernel(const float* __restrict__ x,
                             __nv_bfloat16* __restrict__ A2, int Kin)
{
    int i = blockIdx.x * blockDim.x + threadIdx.x;
    if (i >= M_PAD * 64) return;
    int m = i >> 6, k = i & 63;
    float v = (m < N_NODES && k < Kin) ? x[(size_t)m * Kin + k] : 0.f;
    __nv_bfloat16 h = __float2bfloat16(v);
    __nv_bfloat16 l = __float2bfloat16(v - __bfloat162float(h));
    __nv_bfloat16* row = A2 + (size_t)m * K1;
    row[k] = h; row[64 + k] = h; row[128 + k] = l;
}
__global__ void cvt_wc_kernel(const float* __restrict__ Wc,
                              __nv_bfloat16* __restrict__ Bt)
{
    int i = blockIdx.x * blockDim.x + threadIdx.x;
    if (i >= 128 * D2) return;
    int k = i >> 7, n = i & 127;
    float v = (n < 49) ? Wc[(size_t)k * 49 + n] : 0.f;
    __nv_bfloat16 h = __float2bfloat16(v);
    __nv_bfloat16 l = __float2bfloat16(v - __bfloat162float(h));
    __nv_bfloat16* row = Bt + (size_t)n * K3;
    row[k] = h; row[512 + k] = l; row[1024 + k] = h;
}

// =================== CSR build (once per launch) ===========================
__global__ void init_deg_kernel(int* deg) {
    int i = blockIdx.x * blockDim.x + threadIdx.x;
    if (i < N_NODES) deg[i] = 1;               // implicit self loop
}
__global__ void hist_kernel(const int* __restrict__ ei, int E, int* deg) {
    int i = blockIdx.x * blockDim.x + threadIdx.x;
    if (i < E) atomicAdd(&deg[ei[(size_t)E + i]], 1);
}
__global__ void scan_kernel(const int* __restrict__ deg, int* __restrict__ off)
{
    __shared__ int sh[1024];
    __shared__ int carry;
    if (threadIdx.x == 0) carry = 0;
    __syncthreads();
    for (int base = 0; base < N_NODES; base += 1024) {
        int i = base + threadIdx.x;
        int v = (i < N_NODES) ? deg[i] : 0;
        sh[threadIdx.x] = v;
        __syncthreads();
#pragma unroll
        for (int d = 1; d < 1024; d <<= 1) {
            int t = (threadIdx.x >= d) ? sh[threadIdx.x - d] : 0;
            __syncthreads();
            sh[threadIdx.x] += t;
            __syncthreads();
        }
        int incl = sh[threadIdx.x] + carry;
        if (i < N_NODES) off[i + 1] = incl;
        __syncthreads();
        if (threadIdx.x == 1023) carry = incl;
        __syncthreads();
    }
    if (threadIdx.x == 0) off[0] = 0;
}
__global__ void copy_off_kernel(const int* __restrict__ off, int* __restrict__ cur) {
    int i = blockIdx.x * blockDim.x + threadIdx.x;
    if (i < N_NODES) cur[i] = off[i];
}
__global__ void scatter_kernel(const int* __restrict__ ei, int E, int ET,
                               int* __restrict__ cur, int* __restrict__ csr)
{
    int i = blockIdx.x * blockDim.x + threadIdx.x;
    if (i >= ET) return;
    int src, dst;
    if (i < E) { src = ei[i]; dst = ei[(size_t)E + i]; }
    else       { src = dst = i - E; }
    int pos = atomicAdd(&cur[dst], 1);
    csr[pos] = src;
}

// ============ fused GAT edge layer: one warp per destination node ==========
__global__ void __launch_bounds__(256)
gat_edge_fused_kernel(const float* __restrict__ xl,
                      const float* __restrict__ xr,
                      const int* __restrict__ off,
                      const int* __restrict__ csr,
                      const float* __restrict__ att,
                      const float* __restrict__ bias,
                      __nv_bfloat16* __restrict__ a2)
{
    const int wid  = threadIdx.x >> 5;
    const int lane = threadIdx.x & 31;
    const int node = blockIdx.x * 8 + wid;
    if (node >= N_NODES) return;

    const float4* at4 = (const float4*)att;
    const float4* xr4 = (const float4*)(xr + (size_t)node * D2);
    const float4* b4  = (const float4*)bias;

    float4 attf[HEADS], xrf[HEADS], accf[HEADS];
    float  den[HEADS];
#pragma unroll
    for (int h = 0; h < HEADS; h++) {
        attf[h] = at4[h * 32 + lane];
        xrf[h]  = xr4[h * 32 + lane];
        accf[h] = make_float4(0.f, 0.f, 0.f, 0.f);
        den[h]  = 0.f;
    }

    const int s = off[node], e = off[node + 1];
    for (int i = s; i < e; i++) {
        int src = csr[i];
        const float4* xl4 = (const float4*)(xl + (size_t)src * D2);
        float4 xlf[HEADS];
        float  lg[HEADS];
#pragma unroll
        for (int h = 0; h < HEADS; h++) {
            float4 v = xl4[h * 32 + lane];
            xlf[h] = v;
            float ax = v.x + xrf[h].x; ax = ax > 0.f ? ax : NEG * ax;
            float ay = v.y + xrf[h].y; ay = ay > 0.f ? ay : NEG * ay;
            float az = v.z + xrf[h].z; az = az > 0.f ? az : NEG * az;
            float aw = v.w + xrf[h].w; aw = aw > 0.f ? aw : NEG * aw;
            lg[h] = ax * attf[h].x + ay * attf[h].y + az * attf[h].z + aw * attf[h].w;
        }
#pragma unroll
        for (int o = 16; o > 0; o >>= 1)
#pragma unroll
            for (int h = 0; h < HEADS; h++)
                lg[h] += __shfl_xor_sync(0xffffffffu, lg[h], o);
#pragma unroll
        for (int h = 0; h < HEADS; h++) {
            float pv = __expf(lg[h]);
            den[h] += pv;
            accf[h].x = fmaf(pv, xlf[h].x, accf[h].x);
            accf[h].y = fmaf(pv, xlf[h].y, accf[h].y);
            accf[h].z = fmaf(pv, xlf[h].z, accf[h].z);
            accf[h].w = fmaf(pv, xlf[h].w, accf[h].w);
        }
    }

    __nv_bfloat16* arow = a2 + (size_t)node * K3;
#pragma unroll
    for (int h = 0; h < HEADS; h++) {
        float4 bb = b4[h * 32 + lane];
        float  r  = 1.f / den[h];
        float ox = fmaf(accf[h].x, r, bb.x); ox = ox > 0.f ? ox : expm1f(ox);
        float oy = fmaf(accf[h].y, r, bb.y); oy = oy > 0.f ? oy : expm1f(oy);
        float oz = fmaf(accf[h].z, r, bb.z); oz = oz > 0.f ? oz : expm1f(oz);
        float ow = fmaf(accf[h].w, r, bb.w); ow = ow > 0.f ? ow : expm1f(ow);

        __nv_bfloat16 h0 = __float2bfloat16(ox), h1 = __float2bfloat16(oy);
        __nv_bfloat16 h2 = __float2bfloat16(oz), h3 = __float2bfloat16(ow);
        __nv_bfloat16 l0 = __float2bfloat16(ox - __bfloat162float(h0));
        __nv_bfloat16 l1 = __float2bfloat16(oy - __bfloat162float(h1));
        __nv_bfloat16 l2 = __float2bfloat16(oz - __bfloat162float(h2));
        __nv_bfloat16 l3 = __float2bfloat16(ow - __bfloat162float(h3));

        __nv_bfloat162 hp0 = __halves2bfloat162(h0, h1);
        __nv_bfloat162 hp1 = __halves2bfloat162(h2, h3);
        __nv_bfloat162 lp0 = __halves2bfloat162(l0, l1);
        __nv_bfloat162 lp1 = __halves2bfloat162(l2, l3);
        uint2 hv, lv;
        memcpy(&hv.x, &hp0, 4); memcpy(&hv.y, &hp1, 4);
        memcpy(&lv.x, &lp0, 4); memcpy(&lv.y, &lp1, 4);

        int k = h * 128 + lane * 4;
        *(uint2*)(arow + k)        = hv;
        *(uint2*)(arow + 512 + k)  = hv;
        *(uint2*)(arow + 1024 + k) = lv;
    }
}

// ---------------- host orchestration ---------------------------------------
extern "C" void kernel_launch(void* const* d_in, const int* in_sizes, int n_in,
                              void* d_out, int out_size)
{
    const float* x    = (const float*)d_in[0];
    const int*   ei   = (const int*)d_in[1];
    const float* W1l  = (const float*)d_in[2];
    const float* W1r  = (const float*)d_in[3];
    const float* att1 = (const float*)d_in[4];
    const float* b1   = (const float*)d_in[5];
    const float* W2l  = (const float*)d_in[6];
    const float* W2r  = (const float*)d_in[7];
    const float* att2 = (const float*)d_in[8];
    const float* b2   = (const float*)d_in[9];
    const float* Wc   = (const float*)d_in[10];
    const float* bc   = (const float*)d_in[11];

    const int E    = in_sizes[1] / 2;
    const int ET   = E + N_NODES;
    const int K_in = in_sizes[0] / N_NODES;   // 55

    float *xl, *xr;
    __nv_bfloat16 *a2, *ax2, *btl, *btr, *bw1l, *bw1r, *btc;
    int *deg, *off, *cur, *csr;
    cudaGetSymbolAddress((void**)&xl,   g_xl);
    cudaGetSymbolAddress((void**)&xr,   g_xr);
    cudaGetSymbolAddress((void**)&a2,   g_a2);
    cudaGetSymbolAddress((void**)&ax2,  g_ax2);
    cudaGetSymbolAddress((void**)&btl,  g_btl);
    cudaGetSymbolAddress((void**)&btr,  g_btr);
    cudaGetSymbolAddress((void**)&bw1l, g_bw1l);
    cudaGetSymbolAddress((void**)&bw1r, g_bw1r);
    cudaGetSymbolAddress((void**)&btc,  g_btc);
    cudaGetSymbolAddress((void**)&deg,  g_deg);
    cudaGetSymbolAddress((void**)&off,  g_off);
    cudaGetSymbolAddress((void**)&cur,  g_cur);
    cudaGetSymbolAddress((void**)&csr,  g_csr);

    cudaFuncSetAttribute(mma_gemm_dual_kernel<K3>,
                         cudaFuncAttributeMaxDynamicSharedMemorySize, 98304);
    cudaFuncSetAttribute(mma_gemm_dual_kernel<K1>,
                         cudaFuncAttributeMaxDynamicSharedMemorySize, 98304);
    cudaFuncSetAttribute(mma_gemm_kernel<K3>,
                         cudaFuncAttributeMaxDynamicSharedMemorySize, 65536);

    // ---- CSR build (dst-grouped edges, reused by all 3 layers) ----
    init_deg_kernel<<<(N_NODES + 255) / 256, 256>>>(deg);
    hist_kernel<<<(E + 255) / 256, 256>>>(ei, E, deg);
    scan_kernel<<<1, 1024>>>(deg, off);
    copy_off_kernel<<<(N_NODES + 255) / 256, 256>>>(off, cur);
    scatter_kernel<<<(ET + 255) / 256, 256>>>(ei, E, ET, cur, csr);

    // ---- one-time splits ----
    cvt_w2_kernel<<<(D2 * D2 + 255) / 256, 256>>>(W2l, btl);
    cvt_w2_kernel<<<(D2 * D2 + 255) / 256, 256>>>(W2r, btr);
    cvt_w1_kernel<<<(D2 * 64 + 255) / 256, 256>>>(W1l, bw1l, K_in);
    cvt_w1_kernel<<<(D2 * 64 + 255) / 256, 256>>>(W1r, bw1r, K_in);
    cvt_x_kernel<<<(M_PAD * 64 + 255) / 256, 256>>>(x, ax2, K_in);
    cvt_wc_kernel<<<(128 * D2 + 255) / 256, 256>>>(Wc, btc);

    const int ngrid = (N_NODES + 7) / 8;
    dim3 tg(D2 / 128, M_PAD / 128);   // (4, 391)

    // ---- layer 1 ----
    mma_gemm_dual_kernel<K1><<<tg, 256, 98304>>>(ax2, bw1l, bw1r, xl, xr);
    gat_edge_fused_kernel<<<ngrid, 256>>>(xl, xr, off, csr, att1, b1, a2);

    // ---- layer 2 ----
    mma_gemm_dual_kernel<K3><<<tg, 256, 98304>>>(a2, btl, btr, xl, xr);
    gat_edge_fused_kernel<<<ngrid, 256>>>(xl, xr, off, csr, att2, b2, a2);

    // ---- layer 3 (conv2 again) ----
    mma_gemm_dual_kernel<K3><<<tg, 256, 98304>>>(a2, btl, btr, xl, xr);
    gat_edge_fused_kernel<<<ngrid, 256>>>(xl, xr, off, csr, att2, b2, a2);

    // ---- classifier: d_out = h @ Wc + bc  (49 cols, bounded epilogue) ----
    dim3 gc(1, M_PAD / 128);
    mma_gemm_kernel<K3><<<gc, 256, 65536>>>(a2, btc, (float*)d_out, 49, N_NODES, bc);
}

// round 13
// speedup vs baseline: 3.0672x; 1.0080x over previous
#include <cuda_runtime.h>
#include <cuda_bf16.h>
#include <math.h>
#include <stdint.h>

#define N_NODES 50000
#define M_PAD   50048          // 391 * 128
#define D2      512
#define HEADS   4
#define NEG     0.2f
#define MAXE    450048
#define BK      64             // bf16 K-elems per smem stage (128B rows, SW128)

// K-split: A stored [hi|lo] (width 2*KU), B stored [Bhi|Blo|Bhi] (width 3*KU).
// Stage s in [0,3*NU): pairs A(hi,s%NU)xB(s) for s<2NU, A(lo)xB(hi) after.
#define KU3 512                // layers 2/3 + classifier
#define KU1 64                 // layer 1 (K=55 padded)

// ---------------- scratch (static device globals; zero-initialized) -------
__device__ __align__(128) float g_xl  [(size_t)M_PAD * D2];
__device__ __align__(128) float g_xr  [(size_t)M_PAD * D2];
__device__ __align__(128) __nv_bfloat16 g_a2  [(size_t)M_PAD * (2 * KU3)]; // act split [hi|lo]
__device__ __align__(128) __nv_bfloat16 g_ax2 [(size_t)M_PAD * (2 * KU1)]; // x split [hi|lo]
__device__ __align__(128) __nv_bfloat16 g_btl [(size_t)D2 * (3 * KU3)];    // W2l [hi|lo|hi]
__device__ __align__(128) __nv_bfloat16 g_btr [(size_t)D2 * (3 * KU3)];    // W2r
__device__ __align__(128) __nv_bfloat16 g_bw1l[(size_t)D2 * (3 * KU1)];    // W1l
__device__ __align__(128) __nv_bfloat16 g_bw1r[(size_t)D2 * (3 * KU1)];    // W1r
__device__ __align__(128) __nv_bfloat16 g_btc [(size_t)128 * (3 * KU3)];   // Wc (49 -> 128 rows)
__device__ int g_deg[N_NODES];
__device__ int g_off[N_NODES + 1];
__device__ int g_cur[N_NODES];
__device__ int g_csr[MAXE];

// ======================= helpers ===========================================
__device__ __forceinline__ uint32_t smem_u32(const void* p) {
    uint32_t a;
    asm("{ .reg .u64 t; cvta.to.shared.u64 t, %1; cvt.u32.u64 %0, t; }"
        : "=r"(a) : "l"(p));
    return a;
}
__device__ __forceinline__ uint32_t tile_addr(int r, int kb) {
    return (uint32_t)(r * 128 + ((((kb >> 4) ^ (r & 7))) << 4) + (kb & 15));
}
#define SW128(o) ((o) ^ (((o) >> 3) & 0x70))

__device__ __forceinline__ void mma16816(float* c, const uint32_t* a, const uint32_t* b) {
    asm volatile(
        "mma.sync.aligned.m16n8k16.row.col.f32.bf16.bf16.f32 "
        "{%0,%1,%2,%3}, {%4,%5,%6,%7}, {%8,%9}, {%0,%1,%2,%3};"
        : "+f"(c[0]), "+f"(c[1]), "+f"(c[2]), "+f"(c[3])
        : "r"(a[0]), "r"(a[1]), "r"(a[2]), "r"(a[3]), "r"(b[0]), "r"(b[1]));
}
__device__ __forceinline__ void ldsm_x4(uint32_t& r0, uint32_t& r1,
                                        uint32_t& r2, uint32_t& r3, uint32_t addr) {
    asm volatile("ldmatrix.sync.aligned.m8n8.x4.shared.b16 {%0,%1,%2,%3}, [%4];"
                 : "=r"(r0), "=r"(r1), "=r"(r2), "=r"(r3) : "r"(addr));
}

// 16KB tile loader: 128 rows x 128 bytes, SW128-swizzled, 256 threads.
// W = row width of the gmem matrix in bf16 elements.
template <int W>
__device__ __forceinline__ void load_tile(uint32_t sdst, const __nv_bfloat16* __restrict__ g,
                                          size_t row0, int k0) {
    const char* gb = (const char*)g + (row0 * (size_t)W + (size_t)k0) * 2;
#pragma unroll
    for (int i = 0; i < 4; i++) {
        int c = threadIdx.x + i * 256;       // 1024 16B chunks
        int r = c >> 3;
        int o = (c & 7) * 16;
        uint32_t dst = sdst + SW128((uint32_t)(r * 128 + o));
        asm volatile("cp.async.cg.shared.global [%0], [%1], 16;"
                     :: "r"(dst), "l"(gb + (size_t)r * (W * 2) + o) : "memory");
    }
}

// A-side k offset for stage s (A = [hi|lo], width 2*KU)
template <int KU>
__device__ __forceinline__ int a_koff(int s) {
    constexpr int NU = KU / BK;
    return (s % NU) * BK + ((s >= 2 * NU) ? KU : 0);
}

// ============ fused dual GEMM: CL = A'.BtL^T, CR = A'.BtR^T ================
// 128x128 CTA tile per output, 8 warps (2x4), warp tile 64x32 per output.
// ldmatrix fragment loads; double-buffered cp.async (96KB smem, 1 CTA/SM).
template <int KU>
__global__ void __launch_bounds__(256, 1)
mma_gemm_dual_kernel(const __nv_bfloat16* __restrict__ A2,
                     const __nv_bfloat16* __restrict__ BtL,
                     const __nv_bfloat16* __restrict__ BtR,
                     float* __restrict__ CL, float* __restrict__ CR)
{
    constexpr int NSTG = 3 * KU / BK;
    constexpr int AW   = 2 * KU;
    constexpr int BW   = 3 * KU;
    constexpr int STG  = 49152;              // 48KB per stage
    extern __shared__ char dsm[];
    const int tid    = threadIdx.x;
    const int wid    = tid >> 5;
    const int lane   = tid & 31;
    const int warp_m = wid >> 2;
    const int warp_n = wid & 3;
    const int gID    = lane >> 2;
    const int l4     = lane & 3;
    const size_t m0  = (size_t)blockIdx.y * 128;
    const int    n0  = blockIdx.x * 128;
    const uint32_t smb = smem_u32(dsm);

    // ldmatrix per-lane row/col offsets
    const int a_row = warp_m * 64 + (lane & 15);
    const int a_cb  = (lane >> 4) << 4;                      // 0 or 16
    const int b_row = warp_n * 32 + ((lane >> 4) << 3) + (lane & 7);
    const int b_cb  = ((lane >> 3) & 1) << 4;                // 0 or 16

    float accL[4][4][4], accR[4][4][4];
#pragma unroll
    for (int i = 0; i < 4; i++)
#pragma unroll
        for (int j = 0; j < 4; j++)
#pragma unroll
            for (int q = 0; q < 4; q++) { accL[i][j][q] = 0.f; accR[i][j][q] = 0.f; }

    load_tile<AW>(smb,               A2,  m0, a_koff<KU>(0));
    load_tile<BW>(smb + 16384,       BtL, (size_t)n0, 0);
    load_tile<BW>(smb + 32768,       BtR, (size_t)n0, 0);
    asm volatile("cp.async.commit_group;" ::: "memory");
    load_tile<AW>(smb + STG,         A2,  m0, a_koff<KU>(1));
    load_tile<BW>(smb + STG + 16384, BtL, (size_t)n0, BK);
    load_tile<BW>(smb + STG + 32768, BtR, (size_t)n0, BK);
    asm volatile("cp.async.commit_group;" ::: "memory");

    for (int s = 0; s < NSTG; s++) {
        if (s < NSTG - 1) asm volatile("cp.async.wait_group 1;" ::: "memory");
        else              asm volatile("cp.async.wait_group 0;" ::: "memory");
        __syncthreads();

        const uint32_t As  = smb + (s & 1) * STG;
        const uint32_t BsL = As + 16384;
        const uint32_t BsR = As + 32768;

#pragma unroll
        for (int ks = 0; ks < 4; ks++) {
            const int kb = ks * 32;
            uint32_t a[4][4], bl[4][2], br[4][2];
#pragma unroll
            for (int mf = 0; mf < 4; mf++)
                ldsm_x4(a[mf][0], a[mf][1], a[mf][2], a[mf][3],
                        As + tile_addr(a_row + mf * 16, kb + a_cb));
#pragma unroll
            for (int np = 0; np < 2; np++) {
                ldsm_x4(bl[np*2][0], bl[np*2][1], bl[np*2+1][0], bl[np*2+1][1],
                        BsL + tile_addr(b_row + np * 16, kb + b_cb));
                ldsm_x4(br[np*2][0], br[np*2][1], br[np*2+1][0], br[np*2+1][1],
                        BsR + tile_addr(b_row + np * 16, kb + b_cb));
            }
#pragma unroll
            for (int mf = 0; mf < 4; mf++)
#pragma unroll
                for (int nf = 0; nf < 4; nf++) {
                    mma16816(accL[mf][nf], a[mf], bl[nf]);
                    mma16816(accR[mf][nf], a[mf], br[nf]);
                }
        }
        __syncthreads();

        const int t = s + 2;
        if (t < NSTG) {
            const uint32_t Ps = smb + (s & 1) * STG;
            load_tile<AW>(Ps,          A2,  m0, a_koff<KU>(t));
            load_tile<BW>(Ps + 16384,  BtL, (size_t)n0, t * BK);
            load_tile<BW>(Ps + 32768,  BtR, (size_t)n0, t * BK);
            asm volatile("cp.async.commit_group;" ::: "memory");
        }
    }

    // epilogue: M_PAD multiple of 128 -> no bounds checks
    float* CbL = CL + m0 * D2 + n0;
    float* CbR = CR + m0 * D2 + n0;
#pragma unroll
    for (int mf = 0; mf < 4; mf++) {
        int rr = warp_m * 64 + mf * 16 + gID;
#pragma unroll
        for (int nf = 0; nf < 4; nf++) {
            int cc = warp_n * 32 + nf * 8 + l4 * 2;
            *(float2*)(CbL + (size_t)rr * D2 + cc)       = make_float2(accL[mf][nf][0], accL[mf][nf][1]);
            *(float2*)(CbL + (size_t)(rr + 8) * D2 + cc) = make_float2(accL[mf][nf][2], accL[mf][nf][3]);
            *(float2*)(CbR + (size_t)rr * D2 + cc)       = make_float2(accR[mf][nf][0], accR[mf][nf][1]);
            *(float2*)(CbR + (size_t)(rr + 8) * D2 + cc) = make_float2(accR[mf][nf][2], accR[mf][nf][3]);
        }
    }
}

// ============ single GEMM (classifier): bounded + bias epilogue ============
template <int KU>
__global__ void __launch_bounds__(256, 2)
mma_gemm_kernel(const __nv_bfloat16* __restrict__ A2,
                const __nv_bfloat16* __restrict__ Bt,
                float* __restrict__ C, int ldc, int mrows,
                const float* __restrict__ bias)
{
    constexpr int NSTG = 3 * KU / BK;
    constexpr int AW   = 2 * KU;
    constexpr int BW   = 3 * KU;
    extern __shared__ char dsm[];            // 2 stages x 32KB
    const int tid    = threadIdx.x;
    const int wid    = tid >> 5;
    const int lane   = tid & 31;
    const int warp_m = wid >> 2;
    const int warp_n = wid & 3;
    const int gID    = lane >> 2;
    const int l4     = lane & 3;
    const size_t m0  = (size_t)blockIdx.y * 128;
    const int    n0  = blockIdx.x * 128;
    const uint32_t smb = smem_u32(dsm);

    const int a_row = warp_m * 64 + (lane & 15);
    const int a_cb  = (lane >> 4) << 4;
    const int b_row = warp_n * 32 + ((lane >> 4) << 3) + (lane & 7);
    const int b_cb  = ((lane >> 3) & 1) << 4;

    float acc[4][4][4];
#pragma unroll
    for (int i = 0; i < 4; i++)
#pragma unroll
        for (int j = 0; j < 4; j++)
#pragma unroll
            for (int q = 0; q < 4; q++) acc[i][j][q] = 0.f;

    load_tile<AW>(smb,                 A2, m0, a_koff<KU>(0));
    load_tile<BW>(smb + 16384,         Bt, (size_t)n0, 0);
    asm volatile("cp.async.commit_group;" ::: "memory");
    load_tile<AW>(smb + 32768,         A2, m0, a_koff<KU>(1));
    load_tile<BW>(smb + 32768 + 16384, Bt, (size_t)n0, BK);
    asm volatile("cp.async.commit_group;" ::: "memory");

    for (int s = 0; s < NSTG; s++) {
        if (s < NSTG - 1) asm volatile("cp.async.wait_group 1;" ::: "memory");
        else              asm volatile("cp.async.wait_group 0;" ::: "memory");
        __syncthreads();

        const uint32_t As = smb + (s & 1) * 32768;
        const uint32_t Bs = As + 16384;

#pragma unroll
        for (int ks = 0; ks < 4; ks++) {
            const int kb = ks * 32;
            uint32_t a[4][4], bb[4][2];
#pragma unroll
            for (int mf = 0; mf < 4; mf++)
                ldsm_x4(a[mf][0], a[mf][1], a[mf][2], a[mf][3],
                        As + tile_addr(a_row + mf * 16, kb + a_cb));
#pragma unroll
            for (int np = 0; np < 2; np++)
                ldsm_x4(bb[np*2][0], bb[np*2][1], bb[np*2+1][0], bb[np*2+1][1],
                        Bs + tile_addr(b_row + np * 16, kb + b_cb));
#pragma unroll
            for (int mf = 0; mf < 4; mf++)
#pragma unroll
                for (int nf = 0; nf < 4; nf++)
                    mma16816(acc[mf][nf], a[mf], bb[nf]);
        }
        __syncthreads();

        const int t = s + 2;
        if (t < NSTG) {
            load_tile<AW>(smb + (s & 1) * 32768,         A2, m0, a_koff<KU>(t));
            load_tile<BW>(smb + (s & 1) * 32768 + 16384, Bt, (size_t)n0, t * BK);
            asm volatile("cp.async.commit_group;" ::: "memory");
        }
    }

    // bounded bias epilogue (classifier): ldc == valid output columns
#pragma unroll
    for (int mf = 0; mf < 4; mf++) {
        size_t r0g = m0 + warp_m * 64 + mf * 16 + gID;
#pragma unroll
        for (int nf = 0; nf < 4; nf++) {
            int gcol = n0 + warp_n * 32 + nf * 8 + l4 * 2;
#pragma unroll
            for (int q = 0; q < 2; q++) {
                int c = gcol + q;
                if (c >= ldc) continue;
                float bv = bias[c];
                if (r0g < (size_t)mrows)
                    C[r0g * ldc + c] = acc[mf][nf][q] + bv;
                if (r0g + 8 < (size_t)mrows)
                    C[(r0g + 8) * ldc + c] = acc[mf][nf][2 + q] + bv;
            }
        }
    }
}

// ---------------- one-time weight / input splits ---------------------------
__global__ void cvt_w2_kernel(const float* __restrict__ W,
                              __nv_bfloat16* __restrict__ Bt)
{
    int i = blockIdx.x * blockDim.x + threadIdx.x;
    if (i >= D2 * D2) return;
    int k = i >> 9, n = i & 511;
    float v = W[i];
    __nv_bfloat16 h = __float2bfloat16(v);
    __nv_bfloat16 l = __float2bfloat16(v - __bfloat162float(h));
    __nv_bfloat16* row = Bt + (size_t)n * (3 * KU3);
    row[k] = h; row[KU3 + k] = l; row[2 * KU3 + k] = h;
}
__global__ void cvt_w1_kernel(const float* __restrict__ W,
                              __nv_bfloat16* __restrict__ Bt, int Kin)
{
    int i = blockIdx.x * blockDim.x + threadIdx.x;
    if (i >= D2 * KU1) return;
    int kk = i >> 9, n = i & 511;
    float v = (kk < Kin) ? W[(size_t)kk * D2 + n] : 0.f;
    __nv_bfloat16 h = __float2bfloat16(v);
    __nv_bfloat16 l = __float2bfloat16(v - __bfloat162float(h));
    __nv_bfloat16* row = Bt + (size_t)n * (3 * KU1);
    row[kk] = h; row[KU1 + kk] = l; row[2 * KU1 + kk] = h;
}
__global__ void cvt_x_kernel(const float* __restrict__ x,
                             __nv_bfloat16* __restrict__ A2, int Kin)
{
    int i = blockIdx.x * blockDim.x + threadIdx.x;
    if (i >= M_PAD * KU1) return;
    int m = i >> 6, k = i & 63;
    float v = (m < N_NODES && k < Kin) ? x[(size_t)m * Kin + k] : 0.f;
    __nv_bfloat16 h = __float2bfloat16(v);
    __nv_bfloat16 l = __float2bfloat16(v - __bfloat162float(h));
    __nv_bfloat16* row = A2 + (size_t)m * (2 * KU1);
    row[k] = h; row[KU1 + k] = l;
}
__global__ void cvt_wc_kernel(const float* __restrict__ Wc,
                              __nv_bfloat16* __restrict__ Bt)
{
    int i = blockIdx.x * blockDim.x + threadIdx.x;
    if (i >= 128 * D2) return;
    int k = i >> 7, n = i & 127;
    float v = (n < 49) ? Wc[(size_t)k * 49 + n] : 0.f;
    __nv_bfloat16 h = __float2bfloat16(v);
    __nv_bfloat16 l = __float2bfloat16(v - __bfloat162float(h));
    __nv_bfloat16* row = Bt + (size_t)n * (3 * KU3);
    row[k] = h; row[KU3 + k] = l; row[2 * KU3 + k] = h;
}

// =================== CSR build (once per launch) ===========================
__global__ void init_deg_kernel(int* deg) {
    int i = blockIdx.x * blockDim.x + threadIdx.x;
    if (i < N_NODES) deg[i] = 1;               // implicit self loop
}
__global__ void hist_kernel(const int* __restrict__ ei, int E, int* deg) {
    int i = blockIdx.x * blockDim.x + threadIdx.x;
    if (i < E) atomicAdd(&deg[ei[(size_t)E + i]], 1);
}
__global__ void scan_kernel(const int* __restrict__ deg, int* __restrict__ off)
{
    __shared__ int sh[1024];
    __shared__ int carry;
    if (threadIdx.x == 0) carry = 0;
    __syncthreads();
    for (int base = 0; base < N_NODES; base += 1024) {
        int i = base + threadIdx.x;
        int v = (i < N_NODES) ? deg[i] : 0;
        sh[threadIdx.x] = v;
        __syncthreads();
#pragma unroll
        for (int d = 1; d < 1024; d <<= 1) {
            int t = (threadIdx.x >= d) ? sh[threadIdx.x - d] : 0;
            __syncthreads();
            sh[threadIdx.x] += t;
            __syncthreads();
        }
        int incl = sh[threadIdx.x] + carry;
        if (i < N_NODES) off[i + 1] = incl;
        __syncthreads();
        if (threadIdx.x == 1023) carry = incl;
        __syncthreads();
    }
    if (threadIdx.x == 0) off[0] = 0;
}
__global__ void copy_off_kernel(const int* __restrict__ off, int* __restrict__ cur) {
    int i = blockIdx.x * blockDim.x + threadIdx.x;
    if (i < N_NODES) cur[i] = off[i];
}
__global__ void scatter_kernel(const int* __restrict__ ei, int E, int ET,
                               int* __restrict__ cur, int* __restrict__ csr)
{
    int i = blockIdx.x * blockDim.x + threadIdx.x;
    if (i >= ET) return;
    int src, dst;
    if (i < E) { src = ei[i]; dst = ei[(size_t)E + i]; }
    else       { src = dst = i - E; }
    int pos = atomicAdd(&cur[dst], 1);
    csr[pos] = src;
}

// ============ fused GAT edge layer: one warp per destination node ==========
__global__ void __launch_bounds__(256)
gat_edge_fused_kernel(const float* __restrict__ xl,
                      const float* __restrict__ xr,
                      const int* __restrict__ off,
                      const int* __restrict__ csr,
                      const float* __restrict__ att,
                      const float* __restrict__ bias,
                      __nv_bfloat16* __restrict__ a2)
{
    const int wid  = threadIdx.x >> 5;
    const int lane = threadIdx.x & 31;
    const int node = blockIdx.x * 8 + wid;
    if (node >= N_NODES) return;

    const float4* at4 = (const float4*)att;
    const float4* xr4 = (const float4*)(xr + (size_t)node * D2);
    const float4* b4  = (const float4*)bias;

    float4 attf[HEADS], xrf[HEADS], accf[HEADS];
    float  den[HEADS];
#pragma unroll
    for (int h = 0; h < HEADS; h++) {
        attf[h] = at4[h * 32 + lane];
        xrf[h]  = xr4[h * 32 + lane];
        accf[h] = make_float4(0.f, 0.f, 0.f, 0.f);
        den[h]  = 0.f;
    }

    const int s = off[node], e = off[node + 1];
    for (int i = s; i < e; i++) {
        int src = csr[i];
        const float4* xl4 = (const float4*)(xl + (size_t)src * D2);
        float4 xlf[HEADS];
        float  lg[HEADS];
#pragma unroll
        for (int h = 0; h < HEADS; h++) {
            float4 v = xl4[h * 32 + lane];
            xlf[h] = v;
            float ax = v.x + xrf[h].x; ax = ax > 0.f ? ax : NEG * ax;
            float ay = v.y + xrf[h].y; ay = ay > 0.f ? ay : NEG * ay;
            float az = v.z + xrf[h].z; az = az > 0.f ? az : NEG * az;
            float aw = v.w + xrf[h].w; aw = aw > 0.f ? aw : NEG * aw;
            lg[h] = ax * attf[h].x + ay * attf[h].y + az * attf[h].z + aw * attf[h].w;
        }
#pragma unroll
        for (int o = 16; o > 0; o >>= 1)
#pragma unroll
            for (int h = 0; h < HEADS; h++)
                lg[h] += __shfl_xor_sync(0xffffffffu, lg[h], o);
#pragma unroll
        for (int h = 0; h < HEADS; h++) {
            float pv = __expf(lg[h]);
            den[h] += pv;
            accf[h].x = fmaf(pv, xlf[h].x, accf[h].x);
            accf[h].y = fmaf(pv, xlf[h].y, accf[h].y);
            accf[h].z = fmaf(pv, xlf[h].z, accf[h].z);
            accf[h].w = fmaf(pv, xlf[h].w, accf[h].w);
        }
    }

    __nv_bfloat16* arow = a2 + (size_t)node * (2 * KU3);
#pragma unroll
    for (int h = 0; h < HEADS; h++) {
        float4 bb = b4[h * 32 + lane];
        float  r  = 1.f / den[h];
        float ox = fmaf(accf[h].x, r, bb.x); ox = ox > 0.f ? ox : expm1f(ox);
        float oy = fmaf(accf[h].y, r, bb.y); oy = oy > 0.f ? oy : expm1f(oy);
        float oz = fmaf(accf[h].z, r, bb.z); oz = oz > 0.f ? oz : expm1f(oz);
        float ow = fmaf(accf[h].w, r, bb.w); ow = ow > 0.f ? ow : expm1f(ow);

        __nv_bfloat16 h0 = __float2bfloat16(ox), h1 = __float2bfloat16(oy);
        __nv_bfloat16 h2 = __float2bfloat16(oz), h3 = __float2bfloat16(ow);
        __nv_bfloat16 l0 = __float2bfloat16(ox - __bfloat162float(h0));
        __nv_bfloat16 l1 = __float2bfloat16(oy - __bfloat162float(h1));
        __nv_bfloat16 l2 = __float2bfloat16(oz - __bfloat162float(h2));
        __nv_bfloat16 l3 = __float2bfloat16(ow - __bfloat162float(h3));

        __nv_bfloat162 hp0 = __halves2bfloat162(h0, h1);
        __nv_bfloat162 hp1 = __halves2bfloat162(h2, h3);
        __nv_bfloat162 lp0 = __halves2bfloat162(l0, l1);
        __nv_bfloat162 lp1 = __halves2bfloat162(l2, l3);
        uint2 hv, lv;
        memcpy(&hv.x, &hp0, 4); memcpy(&hv.y, &hp1, 4);
        memcpy(&lv.x, &lp0, 4); memcpy(&lv.y, &lp1, 4);

        int k = h * 128 + lane * 4;
        *(uint2*)(arow + k)       = hv;
        *(uint2*)(arow + KU3 + k) = lv;
    }
}

// ---------------- host orchestration ---------------------------------------
extern "C" void kernel_launch(void* const* d_in, const int* in_sizes, int n_in,
                              void* d_out, int out_size)
{
    const float* x    = (const float*)d_in[0];
    const int*   ei   = (const int*)d_in[1];
    const float* W1l  = (const float*)d_in[2];
    const float* W1r  = (const float*)d_in[3];
    const float* att1 = (const float*)d_in[4];
    const float* b1   = (const float*)d_in[5];
    const float* W2l  = (const float*)d_in[6];
    const float* W2r  = (const float*)d_in[7];
    const float* att2 = (const float*)d_in[8];
    const float* b2   = (const float*)d_in[9];
    const float* Wc   = (const float*)d_in[10];
    const float* bc   = (const float*)d_in[11];

    const int E    = in_sizes[1] / 2;
    const int ET   = E + N_NODES;
    const int K_in = in_sizes[0] / N_NODES;   // 55

    float *xl, *xr;
    __nv_bfloat16 *a2, *ax2, *btl, *btr, *bw1l, *bw1r, *btc;
    int *deg, *off, *cur, *csr;
    cudaGetSymbolAddress((void**)&xl,   g_xl);
    cudaGetSymbolAddress((void**)&xr,   g_xr);
    cudaGetSymbolAddress((void**)&a2,   g_a2);
    cudaGetSymbolAddress((void**)&ax2,  g_ax2);
    cudaGetSymbolAddress((void**)&btl,  g_btl);
    cudaGetSymbolAddress((void**)&btr,  g_btr);
    cudaGetSymbolAddress((void**)&bw1l, g_bw1l);
    cudaGetSymbolAddress((void**)&bw1r, g_bw1r);
    cudaGetSymbolAddress((void**)&btc,  g_btc);
    cudaGetSymbolAddress((void**)&deg,  g_deg);
    cudaGetSymbolAddress((void**)&off,  g_off);
    cudaGetSymbolAddress((void**)&cur,  g_cur);
    cudaGetSymbolAddress((void**)&csr,  g_csr);

    cudaFuncSetAttribute(mma_gemm_dual_kernel<KU3>,
                         cudaFuncAttributeMaxDynamicSharedMemorySize, 98304);
    cudaFuncSetAttribute(mma_gemm_dual_kernel<KU1>,
                         cudaFuncAttributeMaxDynamicSharedMemorySize, 98304);
    cudaFuncSetAttribute(mma_gemm_kernel<KU3>,
                         cudaFuncAttributeMaxDynamicSharedMemorySize, 65536);

    // ---- CSR build (dst-grouped edges, reused by all 3 layers) ----
    init_deg_kernel<<<(N_NODES + 255) / 256, 256>>>(deg);
    hist_kernel<<<(E + 255) / 256, 256>>>(ei, E, deg);
    scan_kernel<<<1, 1024>>>(deg, off);
    copy_off_kernel<<<(N_NODES + 255) / 256, 256>>>(off, cur);
    scatter_kernel<<<(ET + 255) / 256, 256>>>(ei, E, ET, cur, csr);

    // ---- one-time splits ----
    cvt_w2_kernel<<<(D2 * D2 + 255) / 256, 256>>>(W2l, btl);
    cvt_w2_kernel<<<(D2 * D2 + 255) / 256, 256>>>(W2r, btr);
    cvt_w1_kernel<<<(D2 * KU1 + 255) / 256, 256>>>(W1l, bw1l, K_in);
    cvt_w1_kernel<<<(D2 * KU1 + 255) / 256, 256>>>(W1r, bw1r, K_in);
    cvt_x_kernel<<<(M_PAD * KU1 + 255) / 256, 256>>>(x, ax2, K_in);
    cvt_wc_kernel<<<(128 * D2 + 255) / 256, 256>>>(Wc, btc);

    const int ngrid = (N_NODES + 7) / 8;
    dim3 tg(D2 / 128, M_PAD / 128);   // (4, 391)

    // ---- layer 1 ----
    mma_gemm_dual_kernel<KU1><<<tg, 256, 98304>>>(ax2, bw1l, bw1r, xl, xr);
    gat_edge_fused_kernel<<<ngrid, 256>>>(xl, xr, off, csr, att1, b1, a2);

    // ---- layer 2 ----
    mma_gemm_dual_kernel<KU3><<<tg, 256, 98304>>>(a2, btl, btr, xl, xr);
    gat_edge_fused_kernel<<<ngrid, 256>>>(xl, xr, off, csr, att2, b2, a2);

    // ---- layer 3 (conv2 again) ----
    mma_gemm_dual_kernel<KU3><<<tg, 256, 98304>>>(a2, btl, btr, xl, xr);
    gat_edge_fused_kernel<<<ngrid, 256>>>(xl, xr, off, csr, att2, b2, a2);

    // ---- classifier: d_out = h @ Wc + bc  (49 cols, bounded epilogue) ----
    dim3 gc(1, M_PAD / 128);
    mma_gemm_kernel<KU3><<<gc, 256, 65536>>>(a2, btc, (float*)d_out, 49, N_NODES, bc);
}